// round 11
// baseline (speedup 1.0000x reference)
#include <cuda_runtime.h>
#include <cuda_bf16.h>
#include <cuda_fp16.h>
#include <cstdint>

#define DIM    1024
#define NHEADS 16
#define HDIM   64
#define BATCH  2
#define SEQ    2048
#define MROWS  4096

// ---------------------------------------------------------------------------
// Global scratch (static; no runtime allocation)
// x: fp16 2-digit; weights: fp16 1-digit; QKV: fp16 digits
//   [s(3)][bh(32)][seq(2048)][32 u32], Q pre-scaled 0.125.
//   Q: hi+lo used; K: hi only; V: hi+lo used.
// ---------------------------------------------------------------------------
__device__ __align__(128) uint32_t g_xh [MROWS * 512], g_xl [MROWS * 512];
__device__ __align__(128) uint32_t g_wqh[3072 * 512];
__device__ __align__(128) uint32_t g_wph[1024 * 512];
__device__ __align__(128) uint32_t g_aoh[MROWS * 512], g_aol[MROWS * 512];
__device__ __align__(128) uint32_t g_qkvh[3u * 2097152], g_qkvl[3u * 2097152];

// ---------------------------------------------------------------------------
// Helpers
// ---------------------------------------------------------------------------
__device__ __forceinline__ uint32_t smem_u32(const void* p) {
    uint32_t a;
    asm("{ .reg .u64 t; cvta.to.shared.u64 t, %1; cvt.u32.u64 %0, t; }" : "=r"(a) : "l"(p));
    return a;
}
__device__ __forceinline__ void ldsm4(uint32_t r[4], uint32_t addr) {
    asm volatile("ldmatrix.sync.aligned.m8n8.x4.shared.b16 {%0,%1,%2,%3}, [%4];"
                 : "=r"(r[0]), "=r"(r[1]), "=r"(r[2]), "=r"(r[3]) : "r"(addr));
}
__device__ __forceinline__ void ldsm4t(uint32_t r[4], uint32_t addr) {
    asm volatile("ldmatrix.sync.aligned.m8n8.x4.trans.shared.b16 {%0,%1,%2,%3}, [%4];"
                 : "=r"(r[0]), "=r"(r[1]), "=r"(r[2]), "=r"(r[3]) : "r"(addr));
}
__device__ __forceinline__ void mma_h(float c[4], const uint32_t a[4], const uint32_t b[2]) {
    asm volatile(
        "mma.sync.aligned.m16n8k16.row.col.f32.f16.f16.f32 "
        "{%0,%1,%2,%3}, {%4,%5,%6,%7}, {%8,%9}, {%0,%1,%2,%3};"
        : "+f"(c[0]), "+f"(c[1]), "+f"(c[2]), "+f"(c[3])
        : "r"(a[0]), "r"(a[1]), "r"(a[2]), "r"(a[3]), "r"(b[0]), "r"(b[1]));
}
__device__ __forceinline__ uint32_t packh(float x, float y) {
    __half hx = __float2half_rn(x), hy = __float2half_rn(y);
    return (uint32_t)__half_as_ushort(hx) | ((uint32_t)__half_as_ushort(hy) << 16);
}
__device__ __forceinline__ void hilo2h(float x, float y, uint32_t& hi, uint32_t& lo) {
    __half hx = __float2half_rn(x), hy = __float2half_rn(y);
    hi = packh(x, y);
    lo = packh(x - __half2float(hx), y - __half2float(hy));
}
__device__ __forceinline__ void cpa16(uint32_t dst, const void* src) {
    asm volatile("cp.async.cg.shared.global [%0], [%1], 16;" :: "r"(dst), "l"(src));
}
#define CP_COMMIT() asm volatile("cp.async.commit_group;" ::: "memory")
#define CP_WAIT(n)  asm volatile("cp.async.wait_group %0;" :: "n"(n) : "memory")

// ---------------------------------------------------------------------------
// split2h: fp32 [rows][1024] -> fp16 hi/lo packed u32 [rows][512]
// round1h: fp32 -> single fp16 digit
// ---------------------------------------------------------------------------
__global__ __launch_bounds__(256)
void split2h(const float* __restrict__ in, uint32_t* __restrict__ hi,
             uint32_t* __restrict__ lo, int n4)
{
    int g = blockIdx.x * 256 + threadIdx.x;
    if (g >= n4) return;
    float4 v = ((const float4*)in)[g];
    uint32_t h0, l0, h1, l1;
    hilo2h(v.x, v.y, h0, l0);
    hilo2h(v.z, v.w, h1, l1);
    ((uint2*)hi)[g] = make_uint2(h0, h1);
    ((uint2*)lo)[g] = make_uint2(l0, l1);
}
__global__ __launch_bounds__(256)
void round1h(const float* __restrict__ in, uint32_t* __restrict__ hi, int n4)
{
    int g = blockIdx.x * 256 + threadIdx.x;
    if (g >= n4) return;
    float4 v = ((const float4*)in)[g];
    ((uint2*)hi)[g] = make_uint2(packh(v.x, v.y), packh(v.z, v.w));
}

// ---------------------------------------------------------------------------
// GEMM: C[M,N] = A[M,K] @ B[N,K]^T.  A = fp16 2-digit, B = fp16 1-digit.
// 2 MMA terms (HH, LH). Block 128x128, 512 thr, BK=64, 3-stage cp.async.
// smem/stage 48KB: Ahi +0, Alo +16K, Bhi +32K.
// EPI 0: scatter fp16 hi/lo QKV (Q scaled 0.125). EPI 1: fp32 + bias.
// ---------------------------------------------------------------------------
template <int EPI>
__global__ __launch_bounds__(512)
void mm2(const uint32_t* __restrict__ Ah, const uint32_t* __restrict__ Al,
         const uint32_t* __restrict__ Bh,
         const float* __restrict__ bias, float* __restrict__ Cout,
         uint32_t* __restrict__ qh, uint32_t* __restrict__ ql,
         int N, int K)
{
    extern __shared__ __align__(128) uint32_t sm[];
    const int tid = threadIdx.x, lane = tid & 31, wid = tid >> 5;
    const int m0 = blockIdx.y * 128, n0 = blockIdx.x * 128;
    const int wm = (wid & 3) * 32, wn = (wid >> 2) * 32;
    const uint32_t base = smem_u32(sm);
    const int T  = K >> 6;   // k64 steps
    const int KC = K >> 3;   // 16B chunks per row

    const int arow = lane & 15, aco = lane >> 4;
    const int brow = (lane & 7) | ((lane & 16) >> 1), bco = (lane & 8) >> 3;

    auto issue = [&](int t) {
        int st  = t % 3;
        int kc0 = t << 3;
        #pragma unroll
        for (int it = 0; it < 6; it++) {
            int idx = tid + it * 512;              // 0..3071
            int blk = idx >> 10;                   // 0 Ahi, 1 Alo, 2 Bhi
            int row = (idx >> 3) & 127;
            int ch  = idx & 7;
            const uint32_t* sp = (blk == 0) ? Ah : (blk == 1) ? Al : Bh;
            int grow = ((blk == 2) ? n0 : m0) + row;
            const void* src = sp + ((size_t)grow * KC + kc0 + ch) * 4;
            uint32_t dst = base + st * 49152 + blk * 16384
                         + row * 128 + ((ch ^ (row & 7)) * 16);
            cpa16(dst, src);
        }
    };

    float acc[2][4][4] = {};

    issue(0); CP_COMMIT();
    issue(1); CP_COMMIT();

    for (int t = 0; t < T; t++) {
        if (t + 2 < T) { issue(t + 2); CP_COMMIT(); CP_WAIT(2); }
        else           { CP_WAIT(0); }
        __syncthreads();

        const uint32_t sOff = base + (t % 3) * 49152;
        #pragma unroll
        for (int kk = 0; kk < 4; kk++) {
            uint32_t aH[2][4], aL[2][4], bH[2][4];
            #pragma unroll
            for (int mt = 0; mt < 2; mt++) {
                int r = wm + mt * 16 + arow;
                int c = (kk * 2 + aco) ^ (r & 7);
                ldsm4(aH[mt], sOff + r * 128 + c * 16);
                ldsm4(aL[mt], sOff + 16384 + r * 128 + c * 16);
            }
            #pragma unroll
            for (int g = 0; g < 2; g++) {
                int r = wn + g * 16 + brow;
                int c = (kk * 2 + bco) ^ (r & 7);
                ldsm4(bH[g], sOff + 32768 + r * 128 + c * 16);
            }
            #pragma unroll
            for (int mt = 0; mt < 2; mt++)
                #pragma unroll
                for (int nt = 0; nt < 4; nt++)
                    mma_h(acc[mt][nt], aH[mt], &bH[nt >> 1][(nt & 1) * 2]);
            #pragma unroll
            for (int mt = 0; mt < 2; mt++)
                #pragma unroll
                for (int nt = 0; nt < 4; nt++)
                    mma_h(acc[mt][nt], aL[mt], &bH[nt >> 1][(nt & 1) * 2]);
        }
        __syncthreads();
    }

    const int r = lane >> 2, j = (lane & 3) * 2;
    if (EPI == 0) {
        const int sidx = n0 >> 10;
        const float qs = (sidx == 0) ? 0.125f : 1.0f;
        uint32_t* H = qh + (size_t)sidx * 2097152;
        uint32_t* L = ql + (size_t)sidx * 2097152;
        #pragma unroll
        for (int mt = 0; mt < 2; mt++) {
            int mA = m0 + wm + mt * 16 + r;
            int b  = mA >> 11, q = mA & 2047;
            #pragma unroll
            for (int nt = 0; nt < 4; nt++) {
                int n = n0 + wn + nt * 8 + j;
                int rin = n & 1023, h = rin >> 6, d = rin & 63;
                size_t o1 = (((size_t)(b * 16 + h)) * 2048 + q) * 32 + (d >> 1);
                uint32_t hh, ll;
                hilo2h(acc[mt][nt][0] * qs, acc[mt][nt][1] * qs, hh, ll);
                H[o1] = hh; L[o1] = ll;
                hilo2h(acc[mt][nt][2] * qs, acc[mt][nt][3] * qs, hh, ll);
                H[o1 + 8 * 32] = hh; L[o1 + 8 * 32] = ll;
            }
        }
    } else {
        #pragma unroll
        for (int mt = 0; mt < 2; mt++) {
            int mA = m0 + wm + mt * 16 + r;
            #pragma unroll
            for (int nt = 0; nt < 4; nt++) {
                int c = n0 + wn + nt * 8 + j;
                float b0 = bias[c], b1 = bias[c + 1];
                *(float2*)(Cout + (size_t)mA * N + c) =
                    make_float2(acc[mt][nt][0] + b0, acc[mt][nt][1] + b1);
                *(float2*)(Cout + (size_t)(mA + 8) * N + c) =
                    make_float2(acc[mt][nt][2] + b0, acc[mt][nt][3] + b1);
            }
        }
    }
}

// ---------------------------------------------------------------------------
// Flash attention, fp16 HMMA asymmetric 2-term:
//   S: Q 2-digit x K 1-digit (2 MMAs/tile). PV: P 1-digit x V 2-digit.
// Block = 256 queries of one (b,h), 512 thr / 16 warps (warp owns 16 rows).
// smem: Qhi 0 (32KB), Qlo 32768; KV stage s at 65536+s*24576:
//   K +0 (8KB), Vhi +8192, Vlo +16384.  Total 136KB. 3-stage ring, 1 sync/it.
// Epilogue writes fp16 hi/lo AO.
// ---------------------------------------------------------------------------
__global__ __launch_bounds__(512)
void flash2()
{
    extern __shared__ __align__(128) uint32_t sm[];
    const int tid = threadIdx.x, lane = tid & 31, w = tid >> 5;
    const int bh = blockIdx.y, b = bh >> 4, h = bh & 15;
    const int q0 = blockIdx.x * 256;
    const uint32_t base = smem_u32(sm);

    const int arow = lane & 15, aco = lane >> 4;
    const int brow = (lane & 7) | ((lane & 16) >> 1), bco = (lane & 8) >> 3;

    // Q preload (hi+lo): 4096 16B-chunks
    #pragma unroll
    for (int it = 0; it < 8; it++) {
        int idx = tid + it * 512;
        int lohf = idx >= 2048;
        int row = (idx >> 3) & 255, ch = idx & 7;
        const uint32_t* sp = lohf ? g_qkvl : g_qkvh;
        const void* src = sp + ((size_t)bh * 2048 + q0 + row) * 32 + ch * 4;
        uint32_t dst = base + lohf * 32768 + row * 128 + ((ch ^ (row & 7)) * 16);
        cpa16(dst, src);
    }
    CP_COMMIT();

    // KV stage: K hi (8KB) + V hi (8KB) + V lo (8KB) = 1536 chunks
    auto issueKV = [&](int t) {
        int st = t % 3, s0 = t * 64;
        #pragma unroll
        for (int it = 0; it < 3; it++) {
            int idx = tid + it * 512;              // 0..1535
            int part = idx >> 9;                   // 0=K, 1=Vhi, 2=Vlo
            int row = (idx >> 3) & 63, ch = idx & 7;
            const uint32_t* sp = (part == 2) ? g_qkvl : g_qkvh;
            int tensor = (part == 0) ? 1 : 2;
            const void* src = sp + (size_t)tensor * 2097152
                            + ((size_t)bh * 2048 + s0 + row) * 32 + ch * 4;
            uint32_t dst = base + 65536 + st * 24576 + part * 8192
                         + row * 128 + ((ch ^ (row & 7)) * 16);
            cpa16(dst, src);
        }
    };

    issueKV(0); CP_COMMIT();

    float m_a = -1e30f, m_b = -1e30f, l_a = 0.f, l_b = 0.f;
    float o[8][4] = {};

    const int NT = SEQ / 64;   // 32
    for (int t = 0; t < NT; t++) {
        if (t + 1 < NT) { issueKV(t + 1); CP_COMMIT(); CP_WAIT(1); }
        else            { CP_WAIT(0); }
        __syncthreads();

        const uint32_t kBase  = base + 65536 + (t % 3) * 24576;
        const uint32_t vhBase = kBase + 8192;
        const uint32_t vlBase = kBase + 16384;

        // S = Q K^T (Q pre-scaled by 0.125). 2 terms: aH·k, aL·k.
        float s[8][4] = {};
        #pragma unroll
        for (int kk = 0; kk < 4; kk++) {
            uint32_t aH[4], aL[4];
            {
                int r = w * 16 + arow;
                int c = (kk * 2 + aco) ^ (r & 7);
                ldsm4(aH, base + r * 128 + c * 16);
                ldsm4(aL, base + 32768 + r * 128 + c * 16);
            }
            uint32_t bK[4][4];
            #pragma unroll
            for (int g = 0; g < 4; g++) {
                int rb = g * 16 + brow;
                int cb = (kk * 2 + bco) ^ (rb & 7);
                ldsm4(bK[g], kBase + rb * 128 + cb * 16);
            }
            #pragma unroll
            for (int g = 0; g < 4; g++) {
                mma_h(s[2 * g],     aH, &bK[g][0]);
                mma_h(s[2 * g + 1], aH, &bK[g][2]);
            }
            #pragma unroll
            for (int g = 0; g < 4; g++) {
                mma_h(s[2 * g],     aL, &bK[g][0]);
                mma_h(s[2 * g + 1], aL, &bK[g][2]);
            }
        }

        // Online softmax (rows lane>>2 and +8; 4-lane group reduce)
        float mxa = -1e30f, mxb = -1e30f;
        #pragma unroll
        for (int nt = 0; nt < 8; nt++) {
            mxa = fmaxf(mxa, fmaxf(s[nt][0], s[nt][1]));
            mxb = fmaxf(mxb, fmaxf(s[nt][2], s[nt][3]));
        }
        mxa = fmaxf(mxa, __shfl_xor_sync(0xffffffffu, mxa, 1));
        mxa = fmaxf(mxa, __shfl_xor_sync(0xffffffffu, mxa, 2));
        mxb = fmaxf(mxb, __shfl_xor_sync(0xffffffffu, mxb, 1));
        mxb = fmaxf(mxb, __shfl_xor_sync(0xffffffffu, mxb, 2));
        float mna = fmaxf(m_a, mxa), mnb = fmaxf(m_b, mxb);
        float alA = __expf(m_a - mna), alB = __expf(m_b - mnb);
        m_a = mna; m_b = mnb;
        float suma = 0.f, sumb = 0.f;
        #pragma unroll
        for (int nt = 0; nt < 8; nt++) {
            s[nt][0] = __expf(s[nt][0] - mna); suma += s[nt][0];
            s[nt][1] = __expf(s[nt][1] - mna); suma += s[nt][1];
            s[nt][2] = __expf(s[nt][2] - mnb); sumb += s[nt][2];
            s[nt][3] = __expf(s[nt][3] - mnb); sumb += s[nt][3];
        }
        suma += __shfl_xor_sync(0xffffffffu, suma, 1);
        suma += __shfl_xor_sync(0xffffffffu, suma, 2);
        sumb += __shfl_xor_sync(0xffffffffu, sumb, 1);
        sumb += __shfl_xor_sync(0xffffffffu, sumb, 2);
        l_a = l_a * alA + suma;
        l_b = l_b * alB + sumb;
        #pragma unroll
        for (int dt = 0; dt < 8; dt++) {
            o[dt][0] *= alA; o[dt][1] *= alA;
            o[dt][2] *= alB; o[dt][3] *= alB;
        }

        // O += P V  (P 1-digit fp16; V 2-digit: o += pH·vH + pH·vL)
        #pragma unroll
        for (int kc = 0; kc < 4; kc++) {
            uint32_t pH[4];
            pH[0] = packh(s[2 * kc][0],     s[2 * kc][1]);
            pH[1] = packh(s[2 * kc][2],     s[2 * kc][3]);
            pH[2] = packh(s[2 * kc + 1][0], s[2 * kc + 1][1]);
            pH[3] = packh(s[2 * kc + 1][2], s[2 * kc + 1][3]);
            int rv = kc * 16 + arow;
            uint32_t vH[4][4], vL[4][4];
            #pragma unroll
            for (int g = 0; g < 4; g++) {
                int cv = (g * 2 + aco) ^ (rv & 7);
                ldsm4t(vH[g], vhBase + rv * 128 + cv * 16);
                ldsm4t(vL[g], vlBase + rv * 128 + cv * 16);
            }
            #pragma unroll
            for (int g = 0; g < 4; g++) {
                mma_h(o[2 * g],     pH, &vH[g][0]);
                mma_h(o[2 * g + 1], pH, &vH[g][2]);
            }
            #pragma unroll
            for (int g = 0; g < 4; g++) {
                mma_h(o[2 * g],     pH, &vL[g][0]);
                mma_h(o[2 * g + 1], pH, &vL[g][2]);
            }
        }
        // NOTE: no bottom barrier — 3-stage KV ring makes it safe.
    }

    // Epilogue: normalize, pack fp16 hi/lo to g_aoh/g_aol [m][512]
    float ia = 1.f / l_a, ib = 1.f / l_b;
    size_t mA = (size_t)b * SEQ + q0 + w * 16 + (lane >> 2);
    #pragma unroll
    for (int dt = 0; dt < 8; dt++) {
        int c  = dt * 8 + (lane & 3) * 2;
        int ci = h * 32 + (c >> 1);
        uint32_t hh, ll;
        hilo2h(o[dt][0] * ia, o[dt][1] * ia, hh, ll);
        g_aoh[mA * 512 + ci] = hh; g_aol[mA * 512 + ci] = ll;
        hilo2h(o[dt][2] * ib, o[dt][3] * ib, hh, ll);
        g_aoh[(mA + 8) * 512 + ci] = hh; g_aol[(mA + 8) * 512 + ci] = ll;
    }
}

// ---------------------------------------------------------------------------
extern "C" void kernel_launch(void* const* d_in, const int* in_sizes, int n_in,
                              void* d_out, int out_size)
{
    const float* x      = (const float*)d_in[0];
    const float* w_qkv  = (const float*)d_in[1];
    const float* w_proj = (const float*)d_in[2];
    const float* b_proj = (const float*)d_in[3];
    float* out = (float*)d_out;

    void *pxh, *pxl, *pwqh, *pwph, *pqh, *pql, *paoh, *paol;
    cudaGetSymbolAddress(&pxh, g_xh);   cudaGetSymbolAddress(&pxl, g_xl);
    cudaGetSymbolAddress(&pwqh, g_wqh); cudaGetSymbolAddress(&pwph, g_wph);
    cudaGetSymbolAddress(&pqh, g_qkvh); cudaGetSymbolAddress(&pql, g_qkvl);
    cudaGetSymbolAddress(&paoh, g_aoh); cudaGetSymbolAddress(&paol, g_aol);

    cudaFuncSetAttribute(mm2<0>, cudaFuncAttributeMaxDynamicSharedMemorySize, 147456);
    cudaFuncSetAttribute(mm2<1>, cudaFuncAttributeMaxDynamicSharedMemorySize, 147456);
    cudaFuncSetAttribute(flash2, cudaFuncAttributeMaxDynamicSharedMemorySize, 139264);

    // 1) Splits: x -> fp16 2-digit; weights -> fp16 1-digit
    split2h<<<4096, 256>>>(x,      (uint32_t*)pxh, (uint32_t*)pxl, 1048576);
    round1h<<<3072, 256>>>(w_qkv,  (uint32_t*)pwqh, 786432);
    round1h<<<1024, 256>>>(w_proj, (uint32_t*)pwph, 262144);

    // 2) QKV projection (fp16 2-term) -> fp16 hi/lo Q/K/V (Q scaled)
    mm2<0><<<dim3(24, 32), 512, 147456>>>(
        (uint32_t*)pxh, (uint32_t*)pxl, (uint32_t*)pwqh,
        nullptr, nullptr, (uint32_t*)pqh, (uint32_t*)pql, 3072, 1024);

    // 3) Attention (fp16 asymmetric 2-term) -> fp16 hi/lo AO
    flash2<<<dim3(8, 32), 512, 139264>>>();

    // 4) Output projection (fp16 2-term) + bias
    mm2<1><<<dim3(8, 32), 512, 147456>>>(
        (uint32_t*)paoh, (uint32_t*)paol, (uint32_t*)pwph,
        b_proj, out, nullptr, nullptr, 1024, 1024);
}

// round 12
// speedup vs baseline: 1.4942x; 1.4942x over previous
#include <cuda_runtime.h>
#include <cuda_bf16.h>
#include <cuda_fp16.h>
#include <cstdint>

#define DIM    1024
#define NHEADS 16
#define HDIM   64
#define BATCH  2
#define SEQ    2048
#define MROWS  4096

// ---------------------------------------------------------------------------
// Global scratch (static; no runtime allocation)
// x: fp16 2-digit; weights: fp16 1-digit; QKV: fp16 digits
//   [s(3)][bh(32)][seq(2048)][32 u32], Q pre-scaled 0.125.
//   Q: hi+lo used; K: hi only; V: hi+lo used.
// ---------------------------------------------------------------------------
__device__ __align__(128) uint32_t g_xh [MROWS * 512], g_xl [MROWS * 512];
__device__ __align__(128) uint32_t g_wqh[3072 * 512];
__device__ __align__(128) uint32_t g_wph[1024 * 512];
__device__ __align__(128) uint32_t g_aoh[MROWS * 512], g_aol[MROWS * 512];
__device__ __align__(128) uint32_t g_qkvh[3u * 2097152], g_qkvl[3u * 2097152];

// ---------------------------------------------------------------------------
// Helpers
// ---------------------------------------------------------------------------
__device__ __forceinline__ uint32_t smem_u32(const void* p) {
    uint32_t a;
    asm("{ .reg .u64 t; cvta.to.shared.u64 t, %1; cvt.u32.u64 %0, t; }" : "=r"(a) : "l"(p));
    return a;
}
__device__ __forceinline__ void ldsm4(uint32_t r[4], uint32_t addr) {
    asm volatile("ldmatrix.sync.aligned.m8n8.x4.shared.b16 {%0,%1,%2,%3}, [%4];"
                 : "=r"(r[0]), "=r"(r[1]), "=r"(r[2]), "=r"(r[3]) : "r"(addr));
}
__device__ __forceinline__ void ldsm4t(uint32_t r[4], uint32_t addr) {
    asm volatile("ldmatrix.sync.aligned.m8n8.x4.trans.shared.b16 {%0,%1,%2,%3}, [%4];"
                 : "=r"(r[0]), "=r"(r[1]), "=r"(r[2]), "=r"(r[3]) : "r"(addr));
}
__device__ __forceinline__ void mma_h(float c[4], const uint32_t a[4], const uint32_t b[2]) {
    asm volatile(
        "mma.sync.aligned.m16n8k16.row.col.f32.f16.f16.f32 "
        "{%0,%1,%2,%3}, {%4,%5,%6,%7}, {%8,%9}, {%0,%1,%2,%3};"
        : "+f"(c[0]), "+f"(c[1]), "+f"(c[2]), "+f"(c[3])
        : "r"(a[0]), "r"(a[1]), "r"(a[2]), "r"(a[3]), "r"(b[0]), "r"(b[1]));
}
__device__ __forceinline__ uint32_t packh(float x, float y) {
    __half hx = __float2half_rn(x), hy = __float2half_rn(y);
    return (uint32_t)__half_as_ushort(hx) | ((uint32_t)__half_as_ushort(hy) << 16);
}
__device__ __forceinline__ void hilo2h(float x, float y, uint32_t& hi, uint32_t& lo) {
    __half hx = __float2half_rn(x), hy = __float2half_rn(y);
    hi = packh(x, y);
    lo = packh(x - __half2float(hx), y - __half2float(hy));
}
__device__ __forceinline__ void cpa16(uint32_t dst, const void* src) {
    asm volatile("cp.async.cg.shared.global [%0], [%1], 16;" :: "r"(dst), "l"(src));
}
#define CP_COMMIT() asm volatile("cp.async.commit_group;" ::: "memory")
#define CP_WAIT(n)  asm volatile("cp.async.wait_group %0;" :: "n"(n) : "memory")

// ---------------------------------------------------------------------------
// split2h: fp32 [rows][1024] -> fp16 hi/lo packed u32 [rows][512]
// round1h: fp32 -> single fp16 digit
// ---------------------------------------------------------------------------
__global__ __launch_bounds__(256)
void split2h(const float* __restrict__ in, uint32_t* __restrict__ hi,
             uint32_t* __restrict__ lo, int n4)
{
    int g = blockIdx.x * 256 + threadIdx.x;
    if (g >= n4) return;
    float4 v = ((const float4*)in)[g];
    uint32_t h0, l0, h1, l1;
    hilo2h(v.x, v.y, h0, l0);
    hilo2h(v.z, v.w, h1, l1);
    ((uint2*)hi)[g] = make_uint2(h0, h1);
    ((uint2*)lo)[g] = make_uint2(l0, l1);
}
__global__ __launch_bounds__(256)
void round1h(const float* __restrict__ in, uint32_t* __restrict__ hi, int n4)
{
    int g = blockIdx.x * 256 + threadIdx.x;
    if (g >= n4) return;
    float4 v = ((const float4*)in)[g];
    ((uint2*)hi)[g] = make_uint2(packh(v.x, v.y), packh(v.z, v.w));
}

// ---------------------------------------------------------------------------
// GEMM: C[M,N] = A[M,K] @ B[N,K]^T.  A = fp16 2-digit, B = fp16 1-digit.
// 2 MMA terms (HH, LH). Block 128x128, 512 thr, BK=64, 3-stage cp.async.
// smem/stage 48KB: Ahi +0, Alo +16K, Bhi +32K.
// EPI 0: scatter fp16 hi/lo QKV (Q scaled 0.125). EPI 1: fp32 + bias.
// ---------------------------------------------------------------------------
template <int EPI>
__global__ __launch_bounds__(512)
void mm2(const uint32_t* __restrict__ Ah, const uint32_t* __restrict__ Al,
         const uint32_t* __restrict__ Bh,
         const float* __restrict__ bias, float* __restrict__ Cout,
         uint32_t* __restrict__ qh, uint32_t* __restrict__ ql,
         int N, int K)
{
    extern __shared__ __align__(128) uint32_t sm[];
    const int tid = threadIdx.x, lane = tid & 31, wid = tid >> 5;
    const int m0 = blockIdx.y * 128, n0 = blockIdx.x * 128;
    const int wm = (wid & 3) * 32, wn = (wid >> 2) * 32;
    const uint32_t base = smem_u32(sm);
    const int T  = K >> 6;   // k64 steps
    const int KC = K >> 3;   // 16B chunks per row

    const int arow = lane & 15, aco = lane >> 4;
    const int brow = (lane & 7) | ((lane & 16) >> 1), bco = (lane & 8) >> 3;

    auto issue = [&](int t) {
        int st  = t % 3;
        int kc0 = t << 3;
        #pragma unroll
        for (int it = 0; it < 6; it++) {
            int idx = tid + it * 512;              // 0..3071
            int blk = idx >> 10;                   // 0 Ahi, 1 Alo, 2 Bhi
            int row = (idx >> 3) & 127;
            int ch  = idx & 7;
            const uint32_t* sp = (blk == 0) ? Ah : (blk == 1) ? Al : Bh;
            int grow = ((blk == 2) ? n0 : m0) + row;
            const void* src = sp + ((size_t)grow * KC + kc0 + ch) * 4;
            uint32_t dst = base + st * 49152 + blk * 16384
                         + row * 128 + ((ch ^ (row & 7)) * 16);
            cpa16(dst, src);
        }
    };

    float acc[2][4][4] = {};

    issue(0); CP_COMMIT();
    issue(1); CP_COMMIT();

    for (int t = 0; t < T; t++) {
        if (t + 2 < T) { issue(t + 2); CP_COMMIT(); CP_WAIT(2); }
        else           { CP_WAIT(0); }
        __syncthreads();

        const uint32_t sOff = base + (t % 3) * 49152;
        #pragma unroll
        for (int kk = 0; kk < 4; kk++) {
            uint32_t aH[2][4], aL[2][4], bH[2][4];
            #pragma unroll
            for (int mt = 0; mt < 2; mt++) {
                int r = wm + mt * 16 + arow;
                int c = (kk * 2 + aco) ^ (r & 7);
                ldsm4(aH[mt], sOff + r * 128 + c * 16);
                ldsm4(aL[mt], sOff + 16384 + r * 128 + c * 16);
            }
            #pragma unroll
            for (int g = 0; g < 2; g++) {
                int r = wn + g * 16 + brow;
                int c = (kk * 2 + bco) ^ (r & 7);
                ldsm4(bH[g], sOff + 32768 + r * 128 + c * 16);
            }
            #pragma unroll
            for (int mt = 0; mt < 2; mt++)
                #pragma unroll
                for (int nt = 0; nt < 4; nt++)
                    mma_h(acc[mt][nt], aH[mt], &bH[nt >> 1][(nt & 1) * 2]);
            #pragma unroll
            for (int mt = 0; mt < 2; mt++)
                #pragma unroll
                for (int nt = 0; nt < 4; nt++)
                    mma_h(acc[mt][nt], aL[mt], &bH[nt >> 1][(nt & 1) * 2]);
        }
        __syncthreads();
    }

    const int r = lane >> 2, j = (lane & 3) * 2;
    if (EPI == 0) {
        const int sidx = n0 >> 10;
        const float qs = (sidx == 0) ? 0.125f : 1.0f;
        uint32_t* H = qh + (size_t)sidx * 2097152;
        uint32_t* L = ql + (size_t)sidx * 2097152;
        #pragma unroll
        for (int mt = 0; mt < 2; mt++) {
            int mA = m0 + wm + mt * 16 + r;
            int b  = mA >> 11, q = mA & 2047;
            #pragma unroll
            for (int nt = 0; nt < 4; nt++) {
                int n = n0 + wn + nt * 8 + j;
                int rin = n & 1023, h = rin >> 6, d = rin & 63;
                size_t o1 = (((size_t)(b * 16 + h)) * 2048 + q) * 32 + (d >> 1);
                uint32_t hh, ll;
                hilo2h(acc[mt][nt][0] * qs, acc[mt][nt][1] * qs, hh, ll);
                H[o1] = hh; L[o1] = ll;
                hilo2h(acc[mt][nt][2] * qs, acc[mt][nt][3] * qs, hh, ll);
                H[o1 + 8 * 32] = hh; L[o1 + 8 * 32] = ll;
            }
        }
    } else {
        #pragma unroll
        for (int mt = 0; mt < 2; mt++) {
            int mA = m0 + wm + mt * 16 + r;
            #pragma unroll
            for (int nt = 0; nt < 4; nt++) {
                int c = n0 + wn + nt * 8 + j;
                float b0 = bias[c], b1 = bias[c + 1];
                *(float2*)(Cout + (size_t)mA * N + c) =
                    make_float2(acc[mt][nt][0] + b0, acc[mt][nt][1] + b1);
                *(float2*)(Cout + (size_t)(mA + 8) * N + c) =
                    make_float2(acc[mt][nt][2] + b0, acc[mt][nt][3] + b1);
            }
        }
    }
}

// ---------------------------------------------------------------------------
// Flash attention, fp16 HMMA asymmetric 2-term:
//   S: Q 2-digit x K 1-digit (2 MMAs/tile). PV: P 1-digit x V 2-digit.
// Fragments loaded per-g inside each term pass (low register pressure,
// round-10 structure). Block = 256 queries of one (b,h), 512 thr / 16 warps.
// smem: Qhi 0 (32KB), Qlo 32768; KV stage s at 65536+s*24576:
//   K +0 (8KB), Vhi +8192, Vlo +16384.  Total 136KB. 3-stage ring, 1 sync/it.
// Epilogue writes fp16 hi/lo AO.
// ---------------------------------------------------------------------------
__global__ __launch_bounds__(512)
void flash2()
{
    extern __shared__ __align__(128) uint32_t sm[];
    const int tid = threadIdx.x, lane = tid & 31, w = tid >> 5;
    const int bh = blockIdx.y, b = bh >> 4, h = bh & 15;
    const int q0 = blockIdx.x * 256;
    const uint32_t base = smem_u32(sm);

    const int arow = lane & 15, aco = lane >> 4;
    const int brow = (lane & 7) | ((lane & 16) >> 1), bco = (lane & 8) >> 3;

    // Q preload (hi+lo): 4096 16B-chunks
    #pragma unroll
    for (int it = 0; it < 8; it++) {
        int idx = tid + it * 512;
        int lohf = idx >= 2048;
        int row = (idx >> 3) & 255, ch = idx & 7;
        const uint32_t* sp = lohf ? g_qkvl : g_qkvh;
        const void* src = sp + ((size_t)bh * 2048 + q0 + row) * 32 + ch * 4;
        uint32_t dst = base + lohf * 32768 + row * 128 + ((ch ^ (row & 7)) * 16);
        cpa16(dst, src);
    }
    CP_COMMIT();

    // KV stage: K hi (8KB) + V hi (8KB) + V lo (8KB) = 1536 chunks
    auto issueKV = [&](int t) {
        int st = t % 3, s0 = t * 64;
        #pragma unroll
        for (int it = 0; it < 3; it++) {
            int idx = tid + it * 512;              // 0..1535
            int part = idx >> 9;                   // 0=K, 1=Vhi, 2=Vlo
            int row = (idx >> 3) & 63, ch = idx & 7;
            const uint32_t* sp = (part == 2) ? g_qkvl : g_qkvh;
            int tensor = (part == 0) ? 1 : 2;
            const void* src = sp + (size_t)tensor * 2097152
                            + ((size_t)bh * 2048 + s0 + row) * 32 + ch * 4;
            uint32_t dst = base + 65536 + st * 24576 + part * 8192
                         + row * 128 + ((ch ^ (row & 7)) * 16);
            cpa16(dst, src);
        }
    };

    issueKV(0); CP_COMMIT();

    float m_a = -1e30f, m_b = -1e30f, l_a = 0.f, l_b = 0.f;
    float o[8][4] = {};

    const int NT = SEQ / 64;   // 32
    for (int t = 0; t < NT; t++) {
        if (t + 1 < NT) { issueKV(t + 1); CP_COMMIT(); CP_WAIT(1); }
        else            { CP_WAIT(0); }
        __syncthreads();

        const uint32_t kBase  = base + 65536 + (t % 3) * 24576;
        const uint32_t vhBase = kBase + 8192;
        const uint32_t vlBase = kBase + 16384;

        // S = Q K^T (Q pre-scaled by 0.125). 2 terms: aH·k, aL·k.
        float s[8][4] = {};
        #pragma unroll
        for (int kk = 0; kk < 4; kk++) {
            uint32_t aH[4], aL[4];
            {
                int r = w * 16 + arow;
                int c = (kk * 2 + aco) ^ (r & 7);
                ldsm4(aH, base + r * 128 + c * 16);
                ldsm4(aL, base + 32768 + r * 128 + c * 16);
            }
            // Pass 1: aH x K (per-g fragment loads, 8 independent s-tiles)
            #pragma unroll
            for (int g = 0; g < 4; g++) {
                int rb = g * 16 + brow;
                int cb = (kk * 2 + bco) ^ (rb & 7);
                uint32_t bK[4];
                ldsm4(bK, kBase + rb * 128 + cb * 16);
                mma_h(s[2 * g],     aH, &bK[0]);
                mma_h(s[2 * g + 1], aH, &bK[2]);
            }
            // Pass 2: aL x K (re-load fragments; smem has headroom)
            #pragma unroll
            for (int g = 0; g < 4; g++) {
                int rb = g * 16 + brow;
                int cb = (kk * 2 + bco) ^ (rb & 7);
                uint32_t bK[4];
                ldsm4(bK, kBase + rb * 128 + cb * 16);
                mma_h(s[2 * g],     aL, &bK[0]);
                mma_h(s[2 * g + 1], aL, &bK[2]);
            }
        }

        // Online softmax (rows lane>>2 and +8; 4-lane group reduce)
        float mxa = -1e30f, mxb = -1e30f;
        #pragma unroll
        for (int nt = 0; nt < 8; nt++) {
            mxa = fmaxf(mxa, fmaxf(s[nt][0], s[nt][1]));
            mxb = fmaxf(mxb, fmaxf(s[nt][2], s[nt][3]));
        }
        mxa = fmaxf(mxa, __shfl_xor_sync(0xffffffffu, mxa, 1));
        mxa = fmaxf(mxa, __shfl_xor_sync(0xffffffffu, mxa, 2));
        mxb = fmaxf(mxb, __shfl_xor_sync(0xffffffffu, mxb, 1));
        mxb = fmaxf(mxb, __shfl_xor_sync(0xffffffffu, mxb, 2));
        float mna = fmaxf(m_a, mxa), mnb = fmaxf(m_b, mxb);
        float alA = __expf(m_a - mna), alB = __expf(m_b - mnb);
        m_a = mna; m_b = mnb;
        float suma = 0.f, sumb = 0.f;
        #pragma unroll
        for (int nt = 0; nt < 8; nt++) {
            s[nt][0] = __expf(s[nt][0] - mna); suma += s[nt][0];
            s[nt][1] = __expf(s[nt][1] - mna); suma += s[nt][1];
            s[nt][2] = __expf(s[nt][2] - mnb); sumb += s[nt][2];
            s[nt][3] = __expf(s[nt][3] - mnb); sumb += s[nt][3];
        }
        suma += __shfl_xor_sync(0xffffffffu, suma, 1);
        suma += __shfl_xor_sync(0xffffffffu, suma, 2);
        sumb += __shfl_xor_sync(0xffffffffu, sumb, 1);
        sumb += __shfl_xor_sync(0xffffffffu, sumb, 2);
        l_a = l_a * alA + suma;
        l_b = l_b * alB + sumb;
        #pragma unroll
        for (int dt = 0; dt < 8; dt++) {
            o[dt][0] *= alA; o[dt][1] *= alA;
            o[dt][2] *= alB; o[dt][3] *= alB;
        }

        // O += P V  (P 1-digit fp16; V 2-digit; per-g fragment loads)
        #pragma unroll
        for (int kc = 0; kc < 4; kc++) {
            uint32_t pH[4];
            pH[0] = packh(s[2 * kc][0],     s[2 * kc][1]);
            pH[1] = packh(s[2 * kc][2],     s[2 * kc][3]);
            pH[2] = packh(s[2 * kc + 1][0], s[2 * kc + 1][1]);
            pH[3] = packh(s[2 * kc + 1][2], s[2 * kc + 1][3]);
            int rv = kc * 16 + arow;
            // Pass 1: pH x vH
            #pragma unroll
            for (int g = 0; g < 4; g++) {
                int cv = (g * 2 + aco) ^ (rv & 7);
                uint32_t vf[4];
                ldsm4t(vf, vhBase + rv * 128 + cv * 16);
                mma_h(o[2 * g],     pH, &vf[0]);
                mma_h(o[2 * g + 1], pH, &vf[2]);
            }
            // Pass 2: pH x vL
            #pragma unroll
            for (int g = 0; g < 4; g++) {
                int cv = (g * 2 + aco) ^ (rv & 7);
                uint32_t vf[4];
                ldsm4t(vf, vlBase + rv * 128 + cv * 16);
                mma_h(o[2 * g],     pH, &vf[0]);
                mma_h(o[2 * g + 1], pH, &vf[2]);
            }
        }
        // NOTE: no bottom barrier — 3-stage KV ring makes it safe.
    }

    // Epilogue: normalize, pack fp16 hi/lo to g_aoh/g_aol [m][512]
    float ia = 1.f / l_a, ib = 1.f / l_b;
    size_t mA = (size_t)b * SEQ + q0 + w * 16 + (lane >> 2);
    #pragma unroll
    for (int dt = 0; dt < 8; dt++) {
        int c  = dt * 8 + (lane & 3) * 2;
        int ci = h * 32 + (c >> 1);
        uint32_t hh, ll;
        hilo2h(o[dt][0] * ia, o[dt][1] * ia, hh, ll);
        g_aoh[mA * 512 + ci] = hh; g_aol[mA * 512 + ci] = ll;
        hilo2h(o[dt][2] * ib, o[dt][3] * ib, hh, ll);
        g_aoh[(mA + 8) * 512 + ci] = hh; g_aol[(mA + 8) * 512 + ci] = ll;
    }
}

// ---------------------------------------------------------------------------
extern "C" void kernel_launch(void* const* d_in, const int* in_sizes, int n_in,
                              void* d_out, int out_size)
{
    const float* x      = (const float*)d_in[0];
    const float* w_qkv  = (const float*)d_in[1];
    const float* w_proj = (const float*)d_in[2];
    const float* b_proj = (const float*)d_in[3];
    float* out = (float*)d_out;

    void *pxh, *pxl, *pwqh, *pwph, *pqh, *pql, *paoh, *paol;
    cudaGetSymbolAddress(&pxh, g_xh);   cudaGetSymbolAddress(&pxl, g_xl);
    cudaGetSymbolAddress(&pwqh, g_wqh); cudaGetSymbolAddress(&pwph, g_wph);
    cudaGetSymbolAddress(&pqh, g_qkvh); cudaGetSymbolAddress(&pql, g_qkvl);
    cudaGetSymbolAddress(&paoh, g_aoh); cudaGetSymbolAddress(&paol, g_aol);

    cudaFuncSetAttribute(mm2<0>, cudaFuncAttributeMaxDynamicSharedMemorySize, 147456);
    cudaFuncSetAttribute(mm2<1>, cudaFuncAttributeMaxDynamicSharedMemorySize, 147456);
    cudaFuncSetAttribute(flash2, cudaFuncAttributeMaxDynamicSharedMemorySize, 139264);

    // 1) Splits: x -> fp16 2-digit; weights -> fp16 1-digit
    split2h<<<4096, 256>>>(x,      (uint32_t*)pxh, (uint32_t*)pxl, 1048576);
    round1h<<<3072, 256>>>(w_qkv,  (uint32_t*)pwqh, 786432);
    round1h<<<1024, 256>>>(w_proj, (uint32_t*)pwph, 262144);

    // 2) QKV projection (fp16 2-term) -> fp16 hi/lo Q/K/V (Q scaled)
    mm2<0><<<dim3(24, 32), 512, 147456>>>(
        (uint32_t*)pxh, (uint32_t*)pxl, (uint32_t*)pwqh,
        nullptr, nullptr, (uint32_t*)pqh, (uint32_t*)pql, 3072, 1024);

    // 3) Attention (fp16 asymmetric 2-term) -> fp16 hi/lo AO
    flash2<<<dim3(8, 32), 512, 139264>>>();

    // 4) Output projection (fp16 2-term) + bias
    mm2<1><<<dim3(8, 32), 512, 147456>>>(
        (uint32_t*)paoh, (uint32_t*)paol, (uint32_t*)pwph,
        b_proj, out, nullptr, nullptr, 1024, 1024);
}

// round 13
// speedup vs baseline: 1.6905x; 1.1314x over previous
#include <cuda_runtime.h>
#include <cuda_bf16.h>
#include <cuda_fp16.h>
#include <cstdint>

#define DIM    1024
#define NHEADS 16
#define HDIM   64
#define BATCH  2
#define SEQ    2048
#define MROWS  4096

// ---------------------------------------------------------------------------
// Global scratch (static; no runtime allocation)
// x: fp16 2-digit; weights: fp16 1-digit; AO: fp16 1-digit.
// QKV: fp16 digits [s(3)][bh(32)][seq(2048)][32 u32], Q pre-scaled 0.125.
//   Q: hi+lo used; K: hi only; V: hi only.
// ---------------------------------------------------------------------------
__device__ __align__(128) uint32_t g_xh [MROWS * 512], g_xl [MROWS * 512];
__device__ __align__(128) uint32_t g_wqh[3072 * 512];
__device__ __align__(128) uint32_t g_wph[1024 * 512];
__device__ __align__(128) uint32_t g_aoh[MROWS * 512];
__device__ __align__(128) uint32_t g_qkvh[3u * 2097152], g_qkvl[3u * 2097152];

// ---------------------------------------------------------------------------
// Helpers
// ---------------------------------------------------------------------------
__device__ __forceinline__ uint32_t smem_u32(const void* p) {
    uint32_t a;
    asm("{ .reg .u64 t; cvta.to.shared.u64 t, %1; cvt.u32.u64 %0, t; }" : "=r"(a) : "l"(p));
    return a;
}
__device__ __forceinline__ void ldsm4(uint32_t r[4], uint32_t addr) {
    asm volatile("ldmatrix.sync.aligned.m8n8.x4.shared.b16 {%0,%1,%2,%3}, [%4];"
                 : "=r"(r[0]), "=r"(r[1]), "=r"(r[2]), "=r"(r[3]) : "r"(addr));
}
__device__ __forceinline__ void ldsm4t(uint32_t r[4], uint32_t addr) {
    asm volatile("ldmatrix.sync.aligned.m8n8.x4.trans.shared.b16 {%0,%1,%2,%3}, [%4];"
                 : "=r"(r[0]), "=r"(r[1]), "=r"(r[2]), "=r"(r[3]) : "r"(addr));
}
__device__ __forceinline__ void mma_h(float c[4], const uint32_t a[4], const uint32_t b[2]) {
    asm volatile(
        "mma.sync.aligned.m16n8k16.row.col.f32.f16.f16.f32 "
        "{%0,%1,%2,%3}, {%4,%5,%6,%7}, {%8,%9}, {%0,%1,%2,%3};"
        : "+f"(c[0]), "+f"(c[1]), "+f"(c[2]), "+f"(c[3])
        : "r"(a[0]), "r"(a[1]), "r"(a[2]), "r"(a[3]), "r"(b[0]), "r"(b[1]));
}
__device__ __forceinline__ uint32_t packh(float x, float y) {
    __half hx = __float2half_rn(x), hy = __float2half_rn(y);
    return (uint32_t)__half_as_ushort(hx) | ((uint32_t)__half_as_ushort(hy) << 16);
}
__device__ __forceinline__ void hilo2h(float x, float y, uint32_t& hi, uint32_t& lo) {
    __half hx = __float2half_rn(x), hy = __float2half_rn(y);
    hi = packh(x, y);
    lo = packh(x - __half2float(hx), y - __half2float(hy));
}
__device__ __forceinline__ void cpa16(uint32_t dst, const void* src) {
    asm volatile("cp.async.cg.shared.global [%0], [%1], 16;" :: "r"(dst), "l"(src));
}
#define CP_COMMIT() asm volatile("cp.async.commit_group;" ::: "memory")
#define CP_WAIT(n)  asm volatile("cp.async.wait_group %0;" :: "n"(n) : "memory")

// ---------------------------------------------------------------------------
// split2h: fp32 [rows][1024] -> fp16 hi/lo packed u32 [rows][512]
// round1h: fp32 -> single fp16 digit
// ---------------------------------------------------------------------------
__global__ __launch_bounds__(256)
void split2h(const float* __restrict__ in, uint32_t* __restrict__ hi,
             uint32_t* __restrict__ lo, int n4)
{
    int g = blockIdx.x * 256 + threadIdx.x;
    if (g >= n4) return;
    float4 v = ((const float4*)in)[g];
    uint32_t h0, l0, h1, l1;
    hilo2h(v.x, v.y, h0, l0);
    hilo2h(v.z, v.w, h1, l1);
    ((uint2*)hi)[g] = make_uint2(h0, h1);
    ((uint2*)lo)[g] = make_uint2(l0, l1);
}
__global__ __launch_bounds__(256)
void round1h(const float* __restrict__ in, uint32_t* __restrict__ hi, int n4)
{
    int g = blockIdx.x * 256 + threadIdx.x;
    if (g >= n4) return;
    float4 v = ((const float4*)in)[g];
    ((uint2*)hi)[g] = make_uint2(packh(v.x, v.y), packh(v.z, v.w));
}

// ---------------------------------------------------------------------------
// GEMM: C[M,N] = A[M,K] @ B[N,K]^T.  B = fp16 1-digit.
// TERMS=2: A fp16 2-digit (HH+LH MMAs), stage 48KB (Ahi/Alo/Bhi).
// TERMS=1: A fp16 1-digit (HH only), stage 32KB (Ahi/Bhi).
// Block 128x128, 512 thr (16 warps, 32x32 warp tile), BK=64, 3-stage cp.async.
// EPI 0: scatter fp16 hi/lo QKV (Q scaled 0.125). EPI 1: fp32 + bias.
// ---------------------------------------------------------------------------
template <int EPI, int TERMS>
__global__ __launch_bounds__(512)
void mm2(const uint32_t* __restrict__ Ah, const uint32_t* __restrict__ Al,
         const uint32_t* __restrict__ Bh,
         const float* __restrict__ bias, float* __restrict__ Cout,
         uint32_t* __restrict__ qh, uint32_t* __restrict__ ql,
         int N, int K)
{
    extern __shared__ __align__(128) uint32_t sm[];
    const int tid = threadIdx.x, lane = tid & 31, wid = tid >> 5;
    const int m0 = blockIdx.y * 128, n0 = blockIdx.x * 128;
    const int wm = (wid & 3) * 32, wn = (wid >> 2) * 32;
    const uint32_t base = smem_u32(sm);
    const int T  = K >> 6;   // k64 steps
    const int KC = K >> 3;   // 16B chunks per row

    constexpr int STAGE   = (TERMS == 2) ? 49152 : 32768;
    constexpr int B_OFF   = (TERMS == 2) ? 32768 : 16384;
    constexpr int NCHUNKI = (TERMS == 2) ? 6 : 4;

    const int arow = lane & 15, aco = lane >> 4;
    const int brow = (lane & 7) | ((lane & 16) >> 1), bco = (lane & 8) >> 3;

    auto issue = [&](int t) {
        int st  = t % 3;
        int kc0 = t << 3;
        #pragma unroll
        for (int it = 0; it < NCHUNKI; it++) {
            int idx = tid + it * 512;
            int blk = idx >> 10;                   // T2: 0 Ahi,1 Alo,2 Bhi; T1: 0 Ahi,1 Bhi
            int row = (idx >> 3) & 127;
            int ch  = idx & 7;
            const uint32_t* sp;
            int grow;
            if (TERMS == 2) {
                sp   = (blk == 0) ? Ah : (blk == 1) ? Al : Bh;
                grow = ((blk == 2) ? n0 : m0) + row;
            } else {
                sp   = (blk == 0) ? Ah : Bh;
                grow = ((blk == 1) ? n0 : m0) + row;
            }
            const void* src = sp + ((size_t)grow * KC + kc0 + ch) * 4;
            uint32_t dst = base + st * STAGE + blk * 16384
                         + row * 128 + ((ch ^ (row & 7)) * 16);
            cpa16(dst, src);
        }
    };

    float acc[2][4][4] = {};

    issue(0); CP_COMMIT();
    issue(1); CP_COMMIT();

    for (int t = 0; t < T; t++) {
        if (t + 2 < T) { issue(t + 2); CP_COMMIT(); CP_WAIT(2); }
        else           { CP_WAIT(0); }
        __syncthreads();

        const uint32_t sOff = base + (t % 3) * STAGE;
        #pragma unroll
        for (int kk = 0; kk < 4; kk++) {
            uint32_t aH[2][4], aL[2][4], bH[2][4];
            #pragma unroll
            for (int mt = 0; mt < 2; mt++) {
                int r = wm + mt * 16 + arow;
                int c = (kk * 2 + aco) ^ (r & 7);
                ldsm4(aH[mt], sOff + r * 128 + c * 16);
                if (TERMS == 2)
                    ldsm4(aL[mt], sOff + 16384 + r * 128 + c * 16);
            }
            #pragma unroll
            for (int g = 0; g < 2; g++) {
                int r = wn + g * 16 + brow;
                int c = (kk * 2 + bco) ^ (r & 7);
                ldsm4(bH[g], sOff + B_OFF + r * 128 + c * 16);
            }
            #pragma unroll
            for (int mt = 0; mt < 2; mt++)
                #pragma unroll
                for (int nt = 0; nt < 4; nt++)
                    mma_h(acc[mt][nt], aH[mt], &bH[nt >> 1][(nt & 1) * 2]);
            if (TERMS == 2) {
                #pragma unroll
                for (int mt = 0; mt < 2; mt++)
                    #pragma unroll
                    for (int nt = 0; nt < 4; nt++)
                        mma_h(acc[mt][nt], aL[mt], &bH[nt >> 1][(nt & 1) * 2]);
            }
        }
        __syncthreads();
    }

    const int r = lane >> 2, j = (lane & 3) * 2;
    if (EPI == 0) {
        const int sidx = n0 >> 10;
        const float qs = (sidx == 0) ? 0.125f : 1.0f;
        uint32_t* H = qh + (size_t)sidx * 2097152;
        uint32_t* L = ql + (size_t)sidx * 2097152;
        #pragma unroll
        for (int mt = 0; mt < 2; mt++) {
            int mA = m0 + wm + mt * 16 + r;
            int b  = mA >> 11, q = mA & 2047;
            #pragma unroll
            for (int nt = 0; nt < 4; nt++) {
                int n = n0 + wn + nt * 8 + j;
                int rin = n & 1023, h = rin >> 6, d = rin & 63;
                size_t o1 = (((size_t)(b * 16 + h)) * 2048 + q) * 32 + (d >> 1);
                uint32_t hh, ll;
                hilo2h(acc[mt][nt][0] * qs, acc[mt][nt][1] * qs, hh, ll);
                H[o1] = hh; L[o1] = ll;
                hilo2h(acc[mt][nt][2] * qs, acc[mt][nt][3] * qs, hh, ll);
                H[o1 + 8 * 32] = hh; L[o1 + 8 * 32] = ll;
            }
        }
    } else {
        #pragma unroll
        for (int mt = 0; mt < 2; mt++) {
            int mA = m0 + wm + mt * 16 + r;
            #pragma unroll
            for (int nt = 0; nt < 4; nt++) {
                int c = n0 + wn + nt * 8 + j;
                float b0 = bias[c], b1 = bias[c + 1];
                *(float2*)(Cout + (size_t)mA * N + c) =
                    make_float2(acc[mt][nt][0] + b0, acc[mt][nt][1] + b1);
                *(float2*)(Cout + (size_t)(mA + 8) * N + c) =
                    make_float2(acc[mt][nt][2] + b0, acc[mt][nt][3] + b1);
            }
        }
    }
}

// ---------------------------------------------------------------------------
// Flash attention, fp16 HMMA:
//   S: Q 2-digit x K 1-digit (2 MMAs/tile). PV: P 1-digit x V 1-digit (1 MMA).
// Block = 256 queries of one (b,h), 512 thr / 16 warps (warp owns 16 rows).
// smem: Qhi 0 (32KB), Qlo 32768; KV stage s at 65536+s*16384:
//   K +0 (8KB), V +8192.  Total 112KB. 3-stage ring, 1 sync/iter.
// Epilogue writes fp16 1-digit AO.
// ---------------------------------------------------------------------------
__global__ __launch_bounds__(512)
void flash2()
{
    extern __shared__ __align__(128) uint32_t sm[];
    const int tid = threadIdx.x, lane = tid & 31, w = tid >> 5;
    const int bh = blockIdx.y, b = bh >> 4, h = bh & 15;
    const int q0 = blockIdx.x * 256;
    const uint32_t base = smem_u32(sm);

    const int arow = lane & 15, aco = lane >> 4;
    const int brow = (lane & 7) | ((lane & 16) >> 1), bco = (lane & 8) >> 3;

    // Q preload (hi+lo): 4096 16B-chunks
    #pragma unroll
    for (int it = 0; it < 8; it++) {
        int idx = tid + it * 512;
        int lohf = idx >= 2048;
        int row = (idx >> 3) & 255, ch = idx & 7;
        const uint32_t* sp = lohf ? g_qkvl : g_qkvh;
        const void* src = sp + ((size_t)bh * 2048 + q0 + row) * 32 + ch * 4;
        uint32_t dst = base + lohf * 32768 + row * 128 + ((ch ^ (row & 7)) * 16);
        cpa16(dst, src);
    }
    CP_COMMIT();

    // KV stage: K hi (8KB) + V hi (8KB) = 1024 chunks
    auto issueKV = [&](int t) {
        int st = t % 3, s0 = t * 64;
        #pragma unroll
        for (int it = 0; it < 2; it++) {
            int idx = tid + it * 512;              // 0..1023
            int part = idx >> 9;                   // 0=K, 1=V
            int row = (idx >> 3) & 63, ch = idx & 7;
            const void* src = g_qkvh + (size_t)(1 + part) * 2097152
                            + ((size_t)bh * 2048 + s0 + row) * 32 + ch * 4;
            uint32_t dst = base + 65536 + st * 16384 + part * 8192
                         + row * 128 + ((ch ^ (row & 7)) * 16);
            cpa16(dst, src);
        }
    };

    issueKV(0); CP_COMMIT();

    float m_a = -1e30f, m_b = -1e30f, l_a = 0.f, l_b = 0.f;
    float o[8][4] = {};

    const int NT = SEQ / 64;   // 32
    for (int t = 0; t < NT; t++) {
        if (t + 1 < NT) { issueKV(t + 1); CP_COMMIT(); CP_WAIT(1); }
        else            { CP_WAIT(0); }
        __syncthreads();

        const uint32_t kBase = base + 65536 + (t % 3) * 16384;
        const uint32_t vBase = kBase + 8192;

        // S = Q K^T (Q pre-scaled by 0.125). 2 terms: aH·k, aL·k.
        float s[8][4] = {};
        #pragma unroll
        for (int kk = 0; kk < 4; kk++) {
            uint32_t aH[4], aL[4];
            {
                int r = w * 16 + arow;
                int c = (kk * 2 + aco) ^ (r & 7);
                ldsm4(aH, base + r * 128 + c * 16);
                ldsm4(aL, base + 32768 + r * 128 + c * 16);
            }
            #pragma unroll
            for (int g = 0; g < 4; g++) {
                int rb = g * 16 + brow;
                int cb = (kk * 2 + bco) ^ (rb & 7);
                uint32_t bK[4];
                ldsm4(bK, kBase + rb * 128 + cb * 16);
                mma_h(s[2 * g],     aH, &bK[0]);
                mma_h(s[2 * g + 1], aH, &bK[2]);
            }
            #pragma unroll
            for (int g = 0; g < 4; g++) {
                int rb = g * 16 + brow;
                int cb = (kk * 2 + bco) ^ (rb & 7);
                uint32_t bK[4];
                ldsm4(bK, kBase + rb * 128 + cb * 16);
                mma_h(s[2 * g],     aL, &bK[0]);
                mma_h(s[2 * g + 1], aL, &bK[2]);
            }
        }

        // Online softmax (rows lane>>2 and +8; 4-lane group reduce)
        float mxa = -1e30f, mxb = -1e30f;
        #pragma unroll
        for (int nt = 0; nt < 8; nt++) {
            mxa = fmaxf(mxa, fmaxf(s[nt][0], s[nt][1]));
            mxb = fmaxf(mxb, fmaxf(s[nt][2], s[nt][3]));
        }
        mxa = fmaxf(mxa, __shfl_xor_sync(0xffffffffu, mxa, 1));
        mxa = fmaxf(mxa, __shfl_xor_sync(0xffffffffu, mxa, 2));
        mxb = fmaxf(mxb, __shfl_xor_sync(0xffffffffu, mxb, 1));
        mxb = fmaxf(mxb, __shfl_xor_sync(0xffffffffu, mxb, 2));
        float mna = fmaxf(m_a, mxa), mnb = fmaxf(m_b, mxb);
        float alA = __expf(m_a - mna), alB = __expf(m_b - mnb);
        m_a = mna; m_b = mnb;
        float suma = 0.f, sumb = 0.f;
        #pragma unroll
        for (int nt = 0; nt < 8; nt++) {
            s[nt][0] = __expf(s[nt][0] - mna); suma += s[nt][0];
            s[nt][1] = __expf(s[nt][1] - mna); suma += s[nt][1];
            s[nt][2] = __expf(s[nt][2] - mnb); sumb += s[nt][2];
            s[nt][3] = __expf(s[nt][3] - mnb); sumb += s[nt][3];
        }
        suma += __shfl_xor_sync(0xffffffffu, suma, 1);
        suma += __shfl_xor_sync(0xffffffffu, suma, 2);
        sumb += __shfl_xor_sync(0xffffffffu, sumb, 1);
        sumb += __shfl_xor_sync(0xffffffffu, sumb, 2);
        l_a = l_a * alA + suma;
        l_b = l_b * alB + sumb;
        #pragma unroll
        for (int dt = 0; dt < 8; dt++) {
            o[dt][0] *= alA; o[dt][1] *= alA;
            o[dt][2] *= alB; o[dt][3] *= alB;
        }

        // O += P V  (both 1-digit fp16; 1 MMA per tile)
        #pragma unroll
        for (int kc = 0; kc < 4; kc++) {
            uint32_t pH[4];
            pH[0] = packh(s[2 * kc][0],     s[2 * kc][1]);
            pH[1] = packh(s[2 * kc][2],     s[2 * kc][3]);
            pH[2] = packh(s[2 * kc + 1][0], s[2 * kc + 1][1]);
            pH[3] = packh(s[2 * kc + 1][2], s[2 * kc + 1][3]);
            int rv = kc * 16 + arow;
            #pragma unroll
            for (int g = 0; g < 4; g++) {
                int cv = (g * 2 + aco) ^ (rv & 7);
                uint32_t vf[4];
                ldsm4t(vf, vBase + rv * 128 + cv * 16);
                mma_h(o[2 * g],     pH, &vf[0]);
                mma_h(o[2 * g + 1], pH, &vf[2]);
            }
        }
        // NOTE: no bottom barrier — 3-stage KV ring makes it safe.
    }

    // Epilogue: normalize, pack fp16 1-digit to g_aoh [m][512]
    float ia = 1.f / l_a, ib = 1.f / l_b;
    size_t mA = (size_t)b * SEQ + q0 + w * 16 + (lane >> 2);
    #pragma unroll
    for (int dt = 0; dt < 8; dt++) {
        int c  = dt * 8 + (lane & 3) * 2;
        int ci = h * 32 + (c >> 1);
        g_aoh[mA * 512 + ci]       = packh(o[dt][0] * ia, o[dt][1] * ia);
        g_aoh[(mA + 8) * 512 + ci] = packh(o[dt][2] * ib, o[dt][3] * ib);
    }
}

// ---------------------------------------------------------------------------
extern "C" void kernel_launch(void* const* d_in, const int* in_sizes, int n_in,
                              void* d_out, int out_size)
{
    const float* x      = (const float*)d_in[0];
    const float* w_qkv  = (const float*)d_in[1];
    const float* w_proj = (const float*)d_in[2];
    const float* b_proj = (const float*)d_in[3];
    float* out = (float*)d_out;

    void *pxh, *pxl, *pwqh, *pwph, *pqh, *pql, *paoh;
    cudaGetSymbolAddress(&pxh, g_xh);   cudaGetSymbolAddress(&pxl, g_xl);
    cudaGetSymbolAddress(&pwqh, g_wqh); cudaGetSymbolAddress(&pwph, g_wph);
    cudaGetSymbolAddress(&pqh, g_qkvh); cudaGetSymbolAddress(&pql, g_qkvl);
    cudaGetSymbolAddress(&paoh, g_aoh);

    cudaFuncSetAttribute((const void*)mm2<0, 2>, cudaFuncAttributeMaxDynamicSharedMemorySize, 147456);
    cudaFuncSetAttribute((const void*)mm2<1, 1>, cudaFuncAttributeMaxDynamicSharedMemorySize, 98304);
    cudaFuncSetAttribute(flash2, cudaFuncAttributeMaxDynamicSharedMemorySize, 114688);

    // 1) Splits: x -> fp16 2-digit; weights -> fp16 1-digit
    split2h<<<4096, 256>>>(x,      (uint32_t*)pxh, (uint32_t*)pxl, 1048576);
    round1h<<<3072, 256>>>(w_qkv,  (uint32_t*)pwqh, 786432);
    round1h<<<1024, 256>>>(w_proj, (uint32_t*)pwph, 262144);

    // 2) QKV projection (fp16 2-term) -> fp16 hi/lo Q/K/V (Q scaled)
    mm2<0, 2><<<dim3(24, 32), 512, 147456>>>(
        (uint32_t*)pxh, (uint32_t*)pxl, (uint32_t*)pwqh,
        nullptr, nullptr, (uint32_t*)pqh, (uint32_t*)pql, 3072, 1024);

    // 3) Attention (S 2-term, PV 1-term) -> fp16 1-digit AO
    flash2<<<dim3(8, 32), 512, 114688>>>();

    // 4) Output projection (fp16 1-term) + bias
    mm2<1, 1><<<dim3(8, 32), 512, 98304>>>(
        (uint32_t*)paoh, nullptr, (uint32_t*)pwph,
        b_proj, out, nullptr, nullptr, 1024, 1024);
}

// round 14
// speedup vs baseline: 2.3527x; 1.3917x over previous
#include <cuda_runtime.h>
#include <cuda_fp16.h>
#include <cstdint>

#define DIM    1024
#define NHEADS 16
#define HDIM   64
#define BATCH  2
#define SEQ    2048
#define MROWS  4096

// ---------------------------------------------------------------------------
// Global scratch (static; no runtime allocation). Everything fp16 1-digit.
// QKV: [s(3)][bh(32)][seq(2048)][32 u32], Q pre-scaled 0.125.
// ---------------------------------------------------------------------------
__device__ __align__(128) uint32_t g_xh [MROWS * 512];
__device__ __align__(128) uint32_t g_wqh[3072 * 512];
__device__ __align__(128) uint32_t g_wph[1024 * 512];
__device__ __align__(128) uint32_t g_aoh[MROWS * 512];
__device__ __align__(128) uint32_t g_qkvh[3u * 2097152];

// ---------------------------------------------------------------------------
// Helpers
// ---------------------------------------------------------------------------
__device__ __forceinline__ uint32_t smem_u32(const void* p) {
    uint32_t a;
    asm("{ .reg .u64 t; cvta.to.shared.u64 t, %1; cvt.u32.u64 %0, t; }" : "=r"(a) : "l"(p));
    return a;
}
__device__ __forceinline__ void ldsm4(uint32_t r[4], uint32_t addr) {
    asm volatile("ldmatrix.sync.aligned.m8n8.x4.shared.b16 {%0,%1,%2,%3}, [%4];"
                 : "=r"(r[0]), "=r"(r[1]), "=r"(r[2]), "=r"(r[3]) : "r"(addr));
}
__device__ __forceinline__ void ldsm4t(uint32_t r[4], uint32_t addr) {
    asm volatile("ldmatrix.sync.aligned.m8n8.x4.trans.shared.b16 {%0,%1,%2,%3}, [%4];"
                 : "=r"(r[0]), "=r"(r[1]), "=r"(r[2]), "=r"(r[3]) : "r"(addr));
}
__device__ __forceinline__ void mma_h(float c[4], const uint32_t a[4], const uint32_t b[2]) {
    asm volatile(
        "mma.sync.aligned.m16n8k16.row.col.f32.f16.f16.f32 "
        "{%0,%1,%2,%3}, {%4,%5,%6,%7}, {%8,%9}, {%0,%1,%2,%3};"
        : "+f"(c[0]), "+f"(c[1]), "+f"(c[2]), "+f"(c[3])
        : "r"(a[0]), "r"(a[1]), "r"(a[2]), "r"(a[3]), "r"(b[0]), "r"(b[1]));
}
__device__ __forceinline__ uint32_t packh(float x, float y) {
    __half hx = __float2half_rn(x), hy = __float2half_rn(y);
    return (uint32_t)__half_as_ushort(hx) | ((uint32_t)__half_as_ushort(hy) << 16);
}
__device__ __forceinline__ void cpa16(uint32_t dst, const void* src) {
    asm volatile("cp.async.cg.shared.global [%0], [%1], 16;" :: "r"(dst), "l"(src));
}
#define CP_COMMIT() asm volatile("cp.async.commit_group;" ::: "memory")
#define CP_WAIT(n)  asm volatile("cp.async.wait_group %0;" :: "n"(n) : "memory")

// ---------------------------------------------------------------------------
// round1h: fp32 -> single fp16 digit, packed 2/u32
// ---------------------------------------------------------------------------
__global__ __launch_bounds__(256)
void round1h(const float* __restrict__ in, uint32_t* __restrict__ hi, int n4)
{
    int g = blockIdx.x * 256 + threadIdx.x;
    if (g >= n4) return;
    float4 v = ((const float4*)in)[g];
    ((uint2*)hi)[g] = make_uint2(packh(v.x, v.y), packh(v.z, v.w));
}

// ---------------------------------------------------------------------------
// GEMM: C[M,N] = A[M,K] @ B[N,K]^T, both fp16 1-digit, 1 MMA/tile.
// Block 128x128, 512 thr (16 warps, 32x32 warp tile), BK=64, 3-stage cp.async.
// smem/stage 32KB: A +0 (16KB), B +16384.
// EPI 0: scatter fp16 1-digit QKV (Q scaled 0.125). EPI 1: fp32 + bias.
// ---------------------------------------------------------------------------
template <int EPI>
__global__ __launch_bounds__(512)
void mm1(const uint32_t* __restrict__ Ah, const uint32_t* __restrict__ Bh,
         const float* __restrict__ bias, float* __restrict__ Cout,
         uint32_t* __restrict__ qh, int N, int K)
{
    extern __shared__ __align__(128) uint32_t sm[];
    const int tid = threadIdx.x, lane = tid & 31, wid = tid >> 5;
    const int m0 = blockIdx.y * 128, n0 = blockIdx.x * 128;
    const int wm = (wid & 3) * 32, wn = (wid >> 2) * 32;
    const uint32_t base = smem_u32(sm);
    const int T  = K >> 6;   // k64 steps
    const int KC = K >> 3;   // 16B chunks per row

    const int arow = lane & 15, aco = lane >> 4;
    const int brow = (lane & 7) | ((lane & 16) >> 1), bco = (lane & 8) >> 3;

    auto issue = [&](int t) {
        int st  = t % 3;
        int kc0 = t << 3;
        #pragma unroll
        for (int it = 0; it < 4; it++) {
            int idx = tid + it * 512;              // 0..2047: A then B
            int blk = idx >> 10;
            int row = (idx >> 3) & 127;
            int ch  = idx & 7;
            const uint32_t* sp = blk ? Bh : Ah;
            int grow = (blk ? n0 : m0) + row;
            const void* src = sp + ((size_t)grow * KC + kc0 + ch) * 4;
            uint32_t dst = base + st * 32768 + blk * 16384
                         + row * 128 + ((ch ^ (row & 7)) * 16);
            cpa16(dst, src);
        }
    };

    float acc[2][4][4] = {};

    issue(0); CP_COMMIT();
    issue(1); CP_COMMIT();

    for (int t = 0; t < T; t++) {
        if (t + 2 < T) { issue(t + 2); CP_COMMIT(); CP_WAIT(2); }
        else           { CP_WAIT(0); }
        __syncthreads();

        const uint32_t sOff = base + (t % 3) * 32768;
        #pragma unroll
        for (int kk = 0; kk < 4; kk++) {
            uint32_t aH[2][4], bH[2][4];
            #pragma unroll
            for (int mt = 0; mt < 2; mt++) {
                int r = wm + mt * 16 + arow;
                int c = (kk * 2 + aco) ^ (r & 7);
                ldsm4(aH[mt], sOff + r * 128 + c * 16);
            }
            #pragma unroll
            for (int g = 0; g < 2; g++) {
                int r = wn + g * 16 + brow;
                int c = (kk * 2 + bco) ^ (r & 7);
                ldsm4(bH[g], sOff + 16384 + r * 128 + c * 16);
            }
            #pragma unroll
            for (int mt = 0; mt < 2; mt++)
                #pragma unroll
                for (int nt = 0; nt < 4; nt++)
                    mma_h(acc[mt][nt], aH[mt], &bH[nt >> 1][(nt & 1) * 2]);
        }
        __syncthreads();
    }

    const int r = lane >> 2, j = (lane & 3) * 2;
    if (EPI == 0) {
        const int sidx = n0 >> 10;
        const float qs = (sidx == 0) ? 0.125f : 1.0f;
        uint32_t* H = qh + (size_t)sidx * 2097152;
        #pragma unroll
        for (int mt = 0; mt < 2; mt++) {
            int mA = m0 + wm + mt * 16 + r;
            int b  = mA >> 11, q = mA & 2047;
            #pragma unroll
            for (int nt = 0; nt < 4; nt++) {
                int n = n0 + wn + nt * 8 + j;
                int rin = n & 1023, h = rin >> 6, d = rin & 63;
                size_t o1 = (((size_t)(b * 16 + h)) * 2048 + q) * 32 + (d >> 1);
                H[o1]          = packh(acc[mt][nt][0] * qs, acc[mt][nt][1] * qs);
                H[o1 + 8 * 32] = packh(acc[mt][nt][2] * qs, acc[mt][nt][3] * qs);
            }
        }
    } else {
        #pragma unroll
        for (int mt = 0; mt < 2; mt++) {
            int mA = m0 + wm + mt * 16 + r;
            #pragma unroll
            for (int nt = 0; nt < 4; nt++) {
                int c = n0 + wn + nt * 8 + j;
                float b0 = bias[c], b1 = bias[c + 1];
                *(float2*)(Cout + (size_t)mA * N + c) =
                    make_float2(acc[mt][nt][0] + b0, acc[mt][nt][1] + b1);
                *(float2*)(Cout + (size_t)(mA + 8) * N + c) =
                    make_float2(acc[mt][nt][2] + b0, acc[mt][nt][3] + b1);
            }
        }
    }
}

// ---------------------------------------------------------------------------
// Flash attention, plain fp16 HMMA (1 MMA/tile in both phases).
// Block = 256 queries of one (b,h), 512 thr / 16 warps (warp owns 16 rows).
// smem: Q 0 (32KB); KV stage s at 32768+s*16384: K +0 (8KB), V +8192.
// Total 80KB. 3-stage ring, 1 sync/iter. Epilogue writes fp16 1-digit AO.
// ---------------------------------------------------------------------------
__global__ __launch_bounds__(512)
void flash1()
{
    extern __shared__ __align__(128) uint32_t sm[];
    const int tid = threadIdx.x, lane = tid & 31, w = tid >> 5;
    const int bh = blockIdx.y, b = bh >> 4, h = bh & 15;
    const int q0 = blockIdx.x * 256;
    const uint32_t base = smem_u32(sm);

    const int arow = lane & 15, aco = lane >> 4;
    const int brow = (lane & 7) | ((lane & 16) >> 1), bco = (lane & 8) >> 3;

    // Q preload: 2048 16B-chunks (256 rows x 8)
    #pragma unroll
    for (int it = 0; it < 4; it++) {
        int idx = tid + it * 512;
        int row = (idx >> 3) & 255, ch = idx & 7;
        const void* src = g_qkvh + ((size_t)bh * 2048 + q0 + row) * 32 + ch * 4;
        uint32_t dst = base + row * 128 + ((ch ^ (row & 7)) * 16);
        cpa16(dst, src);
    }
    CP_COMMIT();

    // KV stage: K (8KB) + V (8KB) = 1024 chunks
    auto issueKV = [&](int t) {
        int st = t % 3, s0 = t * 64;
        #pragma unroll
        for (int it = 0; it < 2; it++) {
            int idx = tid + it * 512;              // 0..1023
            int part = idx >> 9;                   // 0=K, 1=V
            int row = (idx >> 3) & 63, ch = idx & 7;
            const void* src = g_qkvh + (size_t)(1 + part) * 2097152
                            + ((size_t)bh * 2048 + s0 + row) * 32 + ch * 4;
            uint32_t dst = base + 32768 + st * 16384 + part * 8192
                         + row * 128 + ((ch ^ (row & 7)) * 16);
            cpa16(dst, src);
        }
    };

    issueKV(0); CP_COMMIT();

    float m_a = -1e30f, m_b = -1e30f, l_a = 0.f, l_b = 0.f;
    float o[8][4] = {};

    const int NT = SEQ / 64;   // 32
    for (int t = 0; t < NT; t++) {
        if (t + 1 < NT) { issueKV(t + 1); CP_COMMIT(); CP_WAIT(1); }
        else            { CP_WAIT(0); }
        __syncthreads();

        const uint32_t kBase = base + 32768 + (t % 3) * 16384;
        const uint32_t vBase = kBase + 8192;

        // S = Q K^T (Q pre-scaled by 0.125), 1 MMA/tile
        float s[8][4] = {};
        #pragma unroll
        for (int kk = 0; kk < 4; kk++) {
            uint32_t aH[4];
            {
                int r = w * 16 + arow;
                int c = (kk * 2 + aco) ^ (r & 7);
                ldsm4(aH, base + r * 128 + c * 16);
            }
            #pragma unroll
            for (int g = 0; g < 4; g++) {
                int rb = g * 16 + brow;
                int cb = (kk * 2 + bco) ^ (rb & 7);
                uint32_t bK[4];
                ldsm4(bK, kBase + rb * 128 + cb * 16);
                mma_h(s[2 * g],     aH, &bK[0]);
                mma_h(s[2 * g + 1], aH, &bK[2]);
            }
        }

        // Online softmax (rows lane>>2 and +8; 4-lane group reduce)
        float mxa = -1e30f, mxb = -1e30f;
        #pragma unroll
        for (int nt = 0; nt < 8; nt++) {
            mxa = fmaxf(mxa, fmaxf(s[nt][0], s[nt][1]));
            mxb = fmaxf(mxb, fmaxf(s[nt][2], s[nt][3]));
        }
        mxa = fmaxf(mxa, __shfl_xor_sync(0xffffffffu, mxa, 1));
        mxa = fmaxf(mxa, __shfl_xor_sync(0xffffffffu, mxa, 2));
        mxb = fmaxf(mxb, __shfl_xor_sync(0xffffffffu, mxb, 1));
        mxb = fmaxf(mxb, __shfl_xor_sync(0xffffffffu, mxb, 2));
        float mna = fmaxf(m_a, mxa), mnb = fmaxf(m_b, mxb);
        float alA = __expf(m_a - mna), alB = __expf(m_b - mnb);
        m_a = mna; m_b = mnb;
        float suma = 0.f, sumb = 0.f;
        #pragma unroll
        for (int nt = 0; nt < 8; nt++) {
            s[nt][0] = __expf(s[nt][0] - mna); suma += s[nt][0];
            s[nt][1] = __expf(s[nt][1] - mna); suma += s[nt][1];
            s[nt][2] = __expf(s[nt][2] - mnb); sumb += s[nt][2];
            s[nt][3] = __expf(s[nt][3] - mnb); sumb += s[nt][3];
        }
        suma += __shfl_xor_sync(0xffffffffu, suma, 1);
        suma += __shfl_xor_sync(0xffffffffu, suma, 2);
        sumb += __shfl_xor_sync(0xffffffffu, sumb, 1);
        sumb += __shfl_xor_sync(0xffffffffu, sumb, 2);
        l_a = l_a * alA + suma;
        l_b = l_b * alB + sumb;
        #pragma unroll
        for (int dt = 0; dt < 8; dt++) {
            o[dt][0] *= alA; o[dt][1] *= alA;
            o[dt][2] *= alB; o[dt][3] *= alB;
        }

        // O += P V  (both fp16 1-digit; 1 MMA/tile)
        #pragma unroll
        for (int kc = 0; kc < 4; kc++) {
            uint32_t pH[4];
            pH[0] = packh(s[2 * kc][0],     s[2 * kc][1]);
            pH[1] = packh(s[2 * kc][2],     s[2 * kc][3]);
            pH[2] = packh(s[2 * kc + 1][0], s[2 * kc + 1][1]);
            pH[3] = packh(s[2 * kc + 1][2], s[2 * kc + 1][3]);
            int rv = kc * 16 + arow;
            #pragma unroll
            for (int g = 0; g < 4; g++) {
                int cv = (g * 2 + aco) ^ (rv & 7);
                uint32_t vf[4];
                ldsm4t(vf, vBase + rv * 128 + cv * 16);
                mma_h(o[2 * g],     pH, &vf[0]);
                mma_h(o[2 * g + 1], pH, &vf[2]);
            }
        }
        // NOTE: no bottom barrier — 3-stage KV ring makes it safe.
    }

    // Epilogue: normalize, pack fp16 1-digit to g_aoh [m][512]
    float ia = 1.f / l_a, ib = 1.f / l_b;
    size_t mA = (size_t)b * SEQ + q0 + w * 16 + (lane >> 2);
    #pragma unroll
    for (int dt = 0; dt < 8; dt++) {
        int c  = dt * 8 + (lane & 3) * 2;
        int ci = h * 32 + (c >> 1);
        g_aoh[mA * 512 + ci]       = packh(o[dt][0] * ia, o[dt][1] * ia);
        g_aoh[(mA + 8) * 512 + ci] = packh(o[dt][2] * ib, o[dt][3] * ib);
    }
}

// ---------------------------------------------------------------------------
extern "C" void kernel_launch(void* const* d_in, const int* in_sizes, int n_in,
                              void* d_out, int out_size)
{
    const float* x      = (const float*)d_in[0];
    const float* w_qkv  = (const float*)d_in[1];
    const float* w_proj = (const float*)d_in[2];
    const float* b_proj = (const float*)d_in[3];
    float* out = (float*)d_out;

    void *pxh, *pwqh, *pwph, *pqh, *paoh;
    cudaGetSymbolAddress(&pxh, g_xh);
    cudaGetSymbolAddress(&pwqh, g_wqh);
    cudaGetSymbolAddress(&pwph, g_wph);
    cudaGetSymbolAddress(&pqh, g_qkvh);
    cudaGetSymbolAddress(&paoh, g_aoh);

    cudaFuncSetAttribute((const void*)mm1<0>, cudaFuncAttributeMaxDynamicSharedMemorySize, 98304);
    cudaFuncSetAttribute((const void*)mm1<1>, cudaFuncAttributeMaxDynamicSharedMemorySize, 98304);
    cudaFuncSetAttribute(flash1, cudaFuncAttributeMaxDynamicSharedMemorySize, 81920);

    // 1) Rounds: everything to fp16 1-digit
    round1h<<<4096, 256>>>(x,      (uint32_t*)pxh,  1048576);
    round1h<<<3072, 256>>>(w_qkv,  (uint32_t*)pwqh, 786432);
    round1h<<<1024, 256>>>(w_proj, (uint32_t*)pwph, 262144);

    // 2) QKV projection -> fp16 Q/K/V (Q scaled)
    mm1<0><<<dim3(24, 32), 512, 98304>>>(
        (uint32_t*)pxh, (uint32_t*)pwqh, nullptr, nullptr,
        (uint32_t*)pqh, 3072, 1024);

    // 3) Attention -> fp16 AO
    flash1<<<dim3(8, 32), 512, 81920>>>();

    // 4) Output projection + bias
    mm1<1><<<dim3(8, 32), 512, 98304>>>(
        (uint32_t*)paoh, (uint32_t*)pwph, b_proj, out,
        nullptr, 1024, 1024);
}

// round 15
// speedup vs baseline: 2.6674x; 1.1337x over previous
#include <cuda_runtime.h>
#include <cuda_fp16.h>
#include <cstdint>

#define DIM    1024
#define NHEADS 16
#define HDIM   64
#define BATCH  2
#define SEQ    2048
#define MROWS  4096

// ---------------------------------------------------------------------------
// Global scratch (static; no runtime allocation). Everything fp16 1-digit.
// QKV: [s(3)][bh(32)][seq(2048)][32 u32], Q pre-scaled by 0.125*log2(e).
// ---------------------------------------------------------------------------
__device__ __align__(128) uint32_t g_xh [MROWS * 512];
__device__ __align__(128) uint32_t g_wqh[3072 * 512];
__device__ __align__(128) uint32_t g_wph[1024 * 512];
__device__ __align__(128) uint32_t g_aoh[MROWS * 512];
__device__ __align__(128) uint32_t g_qkvh[3u * 2097152];

// ---------------------------------------------------------------------------
// Helpers
// ---------------------------------------------------------------------------
__device__ __forceinline__ uint32_t smem_u32(const void* p) {
    uint32_t a;
    asm("{ .reg .u64 t; cvta.to.shared.u64 t, %1; cvt.u32.u64 %0, t; }" : "=r"(a) : "l"(p));
    return a;
}
__device__ __forceinline__ void ldsm4(uint32_t r[4], uint32_t addr) {
    asm volatile("ldmatrix.sync.aligned.m8n8.x4.shared.b16 {%0,%1,%2,%3}, [%4];"
                 : "=r"(r[0]), "=r"(r[1]), "=r"(r[2]), "=r"(r[3]) : "r"(addr));
}
__device__ __forceinline__ void ldsm4t(uint32_t r[4], uint32_t addr) {
    asm volatile("ldmatrix.sync.aligned.m8n8.x4.trans.shared.b16 {%0,%1,%2,%3}, [%4];"
                 : "=r"(r[0]), "=r"(r[1]), "=r"(r[2]), "=r"(r[3]) : "r"(addr));
}
__device__ __forceinline__ void mma_h(float c[4], const uint32_t a[4], const uint32_t b[2]) {
    asm volatile(
        "mma.sync.aligned.m16n8k16.row.col.f32.f16.f16.f32 "
        "{%0,%1,%2,%3}, {%4,%5,%6,%7}, {%8,%9}, {%0,%1,%2,%3};"
        : "+f"(c[0]), "+f"(c[1]), "+f"(c[2]), "+f"(c[3])
        : "r"(a[0]), "r"(a[1]), "r"(a[2]), "r"(a[3]), "r"(b[0]), "r"(b[1]));
}
__device__ __forceinline__ uint32_t packh(float x, float y) {
    __half hx = __float2half_rn(x), hy = __float2half_rn(y);
    return (uint32_t)__half_as_ushort(hx) | ((uint32_t)__half_as_ushort(hy) << 16);
}
__device__ __forceinline__ void cpa16(uint32_t dst, const void* src) {
    asm volatile("cp.async.cg.shared.global [%0], [%1], 16;" :: "r"(dst), "l"(src));
}
#define CP_COMMIT() asm volatile("cp.async.commit_group;" ::: "memory")
#define CP_WAIT(n)  asm volatile("cp.async.wait_group %0;" :: "n"(n) : "memory")

// ---------------------------------------------------------------------------
// round_all: fp32 -> fp16 1-digit for all three inputs in ONE launch.
// Blocks [0,4096): x; [4096,7168): w_qkv; [7168,8192): w_proj.
// ---------------------------------------------------------------------------
__global__ __launch_bounds__(256)
void round_all(const float* __restrict__ x, const float* __restrict__ wq,
               const float* __restrict__ wp,
               uint32_t* __restrict__ xh, uint32_t* __restrict__ wqh,
               uint32_t* __restrict__ wph)
{
    int blk = blockIdx.x;
    const float* in;
    uint32_t* outp;
    int gbase;
    if (blk < 4096)      { in = x;  outp = xh;  gbase = blk; }
    else if (blk < 7168) { in = wq; outp = wqh; gbase = blk - 4096; }
    else                 { in = wp; outp = wph; gbase = blk - 7168; }
    int g = gbase * 256 + threadIdx.x;
    float4 v = ((const float4*)in)[g];
    ((uint2*)outp)[g] = make_uint2(packh(v.x, v.y), packh(v.z, v.w));
}

// ---------------------------------------------------------------------------
// GEMM: C[M,N] = A[M,K] @ B[N,K]^T, fp16 1-digit, 1 MMA/tile.
// Block 128x128, 256 thr (8 warps, 64x32 warp tile), BK=64, 3-stage cp.async,
// 2 CTAs/SM. smem/stage 32KB: A +0 (16KB), B +16384.
// EPI 0: scatter fp16 QKV (Q scaled 0.125*log2e). EPI 1: fp32 + bias.
// ---------------------------------------------------------------------------
template <int EPI>
__global__ __launch_bounds__(256, 2)
void mm1(const uint32_t* __restrict__ Ah, const uint32_t* __restrict__ Bh,
         const float* __restrict__ bias, float* __restrict__ Cout,
         uint32_t* __restrict__ qh, int N, int K)
{
    extern __shared__ __align__(128) uint32_t sm[];
    const int tid = threadIdx.x, lane = tid & 31, wid = tid >> 5;
    const int m0 = blockIdx.y * 128, n0 = blockIdx.x * 128;
    const int wm = (wid & 1) * 64, wn = (wid >> 1) * 32;
    const uint32_t base = smem_u32(sm);
    const int T  = K >> 6;   // k64 steps
    const int KC = K >> 3;   // 16B chunks per row

    const int arow = lane & 15, aco = lane >> 4;
    const int brow = (lane & 7) | ((lane & 16) >> 1), bco = (lane & 8) >> 3;

    auto issue = [&](int t) {
        int st  = t % 3;
        int kc0 = t << 3;
        #pragma unroll
        for (int it = 0; it < 8; it++) {
            int idx = tid + it * 256;              // 0..2047: A then B
            int blk = idx >> 10;
            int row = (idx >> 3) & 127;
            int ch  = idx & 7;
            const uint32_t* sp = blk ? Bh : Ah;
            int grow = (blk ? n0 : m0) + row;
            const void* src = sp + ((size_t)grow * KC + kc0 + ch) * 4;
            uint32_t dst = base + st * 32768 + blk * 16384
                         + row * 128 + ((ch ^ (row & 7)) * 16);
            cpa16(dst, src);
        }
    };

    float acc[4][4][4] = {};

    issue(0); CP_COMMIT();
    issue(1); CP_COMMIT();

    for (int t = 0; t < T; t++) {
        if (t + 2 < T) { issue(t + 2); CP_COMMIT(); CP_WAIT(2); }
        else           { CP_WAIT(0); }
        __syncthreads();

        const uint32_t sOff = base + (t % 3) * 32768;
        #pragma unroll
        for (int kk = 0; kk < 4; kk++) {
            uint32_t aH[4][4], bH[2][4];
            #pragma unroll
            for (int mt = 0; mt < 4; mt++) {
                int r = wm + mt * 16 + arow;
                int c = (kk * 2 + aco) ^ (r & 7);
                ldsm4(aH[mt], sOff + r * 128 + c * 16);
            }
            #pragma unroll
            for (int g = 0; g < 2; g++) {
                int r = wn + g * 16 + brow;
                int c = (kk * 2 + bco) ^ (r & 7);
                ldsm4(bH[g], sOff + 16384 + r * 128 + c * 16);
            }
            #pragma unroll
            for (int mt = 0; mt < 4; mt++)
                #pragma unroll
                for (int nt = 0; nt < 4; nt++)
                    mma_h(acc[mt][nt], aH[mt], &bH[nt >> 1][(nt & 1) * 2]);
        }
        __syncthreads();
    }

    const int r = lane >> 2, j = (lane & 3) * 2;
    if (EPI == 0) {
        const int sidx = n0 >> 10;
        // Q pre-scale folds 1/sqrt(64) and log2(e) for base-2 softmax
        const float qs = (sidx == 0) ? 0.125f * 1.44269504f : 1.0f;
        uint32_t* H = qh + (size_t)sidx * 2097152;
        #pragma unroll
        for (int mt = 0; mt < 4; mt++) {
            int mA = m0 + wm + mt * 16 + r;
            int b  = mA >> 11, q = mA & 2047;
            #pragma unroll
            for (int nt = 0; nt < 4; nt++) {
                int n = n0 + wn + nt * 8 + j;
                int rin = n & 1023, h = rin >> 6, d = rin & 63;
                size_t o1 = (((size_t)(b * 16 + h)) * 2048 + q) * 32 + (d >> 1);
                H[o1]          = packh(acc[mt][nt][0] * qs, acc[mt][nt][1] * qs);
                H[o1 + 8 * 32] = packh(acc[mt][nt][2] * qs, acc[mt][nt][3] * qs);
            }
        }
    } else {
        #pragma unroll
        for (int mt = 0; mt < 4; mt++) {
            int mA = m0 + wm + mt * 16 + r;
            #pragma unroll
            for (int nt = 0; nt < 4; nt++) {
                int c = n0 + wn + nt * 8 + j;
                float b0 = bias[c], b1 = bias[c + 1];
                *(float2*)(Cout + (size_t)mA * N + c) =
                    make_float2(acc[mt][nt][0] + b0, acc[mt][nt][1] + b1);
                *(float2*)(Cout + (size_t)(mA + 8) * N + c) =
                    make_float2(acc[mt][nt][2] + b0, acc[mt][nt][3] + b1);
            }
        }
    }
}

// ---------------------------------------------------------------------------
// Flash attention, plain fp16 HMMA, base-2 online softmax (S is log2-domain;
// exp2f everywhere). Block = 256 queries of one (b,h), 512 thr / 16 warps.
// smem: Q 0 (32KB); KV stage s at 32768+s*16384: K +0 (8KB), V +8192.
// Total 80KB. 3-stage ring, 1 sync/iter. Epilogue writes fp16 1-digit AO.
// ---------------------------------------------------------------------------
__global__ __launch_bounds__(512)
void flash1()
{
    extern __shared__ __align__(128) uint32_t sm[];
    const int tid = threadIdx.x, lane = tid & 31, w = tid >> 5;
    const int bh = blockIdx.y, b = bh >> 4, h = bh & 15;
    const int q0 = blockIdx.x * 256;
    const uint32_t base = smem_u32(sm);

    const int arow = lane & 15, aco = lane >> 4;
    const int brow = (lane & 7) | ((lane & 16) >> 1), bco = (lane & 8) >> 3;

    // Q preload: 2048 16B-chunks (256 rows x 8)
    #pragma unroll
    for (int it = 0; it < 4; it++) {
        int idx = tid + it * 512;
        int row = (idx >> 3) & 255, ch = idx & 7;
        const void* src = g_qkvh + ((size_t)bh * 2048 + q0 + row) * 32 + ch * 4;
        uint32_t dst = base + row * 128 + ((ch ^ (row & 7)) * 16);
        cpa16(dst, src);
    }
    CP_COMMIT();

    // KV stage: K (8KB) + V (8KB) = 1024 chunks
    auto issueKV = [&](int t) {
        int st = t % 3, s0 = t * 64;
        #pragma unroll
        for (int it = 0; it < 2; it++) {
            int idx = tid + it * 512;              // 0..1023
            int part = idx >> 9;                   // 0=K, 1=V
            int row = (idx >> 3) & 63, ch = idx & 7;
            const void* src = g_qkvh + (size_t)(1 + part) * 2097152
                            + ((size_t)bh * 2048 + s0 + row) * 32 + ch * 4;
            uint32_t dst = base + 32768 + st * 16384 + part * 8192
                         + row * 128 + ((ch ^ (row & 7)) * 16);
            cpa16(dst, src);
        }
    };

    issueKV(0); CP_COMMIT();

    float m_a = -1e30f, m_b = -1e30f, l_a = 0.f, l_b = 0.f;
    float o[8][4] = {};

    const int NT = SEQ / 64;   // 32
    for (int t = 0; t < NT; t++) {
        if (t + 1 < NT) { issueKV(t + 1); CP_COMMIT(); CP_WAIT(1); }
        else            { CP_WAIT(0); }
        __syncthreads();

        const uint32_t kBase = base + 32768 + (t % 3) * 16384;
        const uint32_t vBase = kBase + 8192;

        // S = Q K^T (log2 domain), 1 MMA/tile
        float s[8][4] = {};
        #pragma unroll
        for (int kk = 0; kk < 4; kk++) {
            uint32_t aH[4];
            {
                int r = w * 16 + arow;
                int c = (kk * 2 + aco) ^ (r & 7);
                ldsm4(aH, base + r * 128 + c * 16);
            }
            #pragma unroll
            for (int g = 0; g < 4; g++) {
                int rb = g * 16 + brow;
                int cb = (kk * 2 + bco) ^ (rb & 7);
                uint32_t bK[4];
                ldsm4(bK, kBase + rb * 128 + cb * 16);
                mma_h(s[2 * g],     aH, &bK[0]);
                mma_h(s[2 * g + 1], aH, &bK[2]);
            }
        }

        // Online softmax, base 2 (rows lane>>2 and +8; 4-lane group reduce)
        float mxa = -1e30f, mxb = -1e30f;
        #pragma unroll
        for (int nt = 0; nt < 8; nt++) {
            mxa = fmaxf(mxa, fmaxf(s[nt][0], s[nt][1]));
            mxb = fmaxf(mxb, fmaxf(s[nt][2], s[nt][3]));
        }
        mxa = fmaxf(mxa, __shfl_xor_sync(0xffffffffu, mxa, 1));
        mxa = fmaxf(mxa, __shfl_xor_sync(0xffffffffu, mxa, 2));
        mxb = fmaxf(mxb, __shfl_xor_sync(0xffffffffu, mxb, 1));
        mxb = fmaxf(mxb, __shfl_xor_sync(0xffffffffu, mxb, 2));
        float mna = fmaxf(m_a, mxa), mnb = fmaxf(m_b, mxb);
        float alA = exp2f(m_a - mna), alB = exp2f(m_b - mnb);
        m_a = mna; m_b = mnb;
        float suma = 0.f, sumb = 0.f;
        #pragma unroll
        for (int nt = 0; nt < 8; nt++) {
            s[nt][0] = exp2f(s[nt][0] - mna); suma += s[nt][0];
            s[nt][1] = exp2f(s[nt][1] - mna); suma += s[nt][1];
            s[nt][2] = exp2f(s[nt][2] - mnb); sumb += s[nt][2];
            s[nt][3] = exp2f(s[nt][3] - mnb); sumb += s[nt][3];
        }
        suma += __shfl_xor_sync(0xffffffffu, suma, 1);
        suma += __shfl_xor_sync(0xffffffffu, suma, 2);
        sumb += __shfl_xor_sync(0xffffffffu, sumb, 1);
        sumb += __shfl_xor_sync(0xffffffffu, sumb, 2);
        l_a = l_a * alA + suma;
        l_b = l_b * alB + sumb;
        #pragma unroll
        for (int dt = 0; dt < 8; dt++) {
            o[dt][0] *= alA; o[dt][1] *= alA;
            o[dt][2] *= alB; o[dt][3] *= alB;
        }

        // O += P V  (both fp16 1-digit; 1 MMA/tile)
        #pragma unroll
        for (int kc = 0; kc < 4; kc++) {
            uint32_t pH[4];
            pH[0] = packh(s[2 * kc][0],     s[2 * kc][1]);
            pH[1] = packh(s[2 * kc][2],     s[2 * kc][3]);
            pH[2] = packh(s[2 * kc + 1][0], s[2 * kc + 1][1]);
            pH[3] = packh(s[2 * kc + 1][2], s[2 * kc + 1][3]);
            int rv = kc * 16 + arow;
            #pragma unroll
            for (int g = 0; g < 4; g++) {
                int cv = (g * 2 + aco) ^ (rv & 7);
                uint32_t vf[4];
                ldsm4t(vf, vBase + rv * 128 + cv * 16);
                mma_h(o[2 * g],     pH, &vf[0]);
                mma_h(o[2 * g + 1], pH, &vf[2]);
            }
        }
        // NOTE: no bottom barrier — 3-stage KV ring makes it safe.
    }

    // Epilogue: normalize, pack fp16 1-digit to g_aoh [m][512]
    float ia = 1.f / l_a, ib = 1.f / l_b;
    size_t mA = (size_t)b * SEQ + q0 + w * 16 + (lane >> 2);
    #pragma unroll
    for (int dt = 0; dt < 8; dt++) {
        int c  = dt * 8 + (lane & 3) * 2;
        int ci = h * 32 + (c >> 1);
        g_aoh[mA * 512 + ci]       = packh(o[dt][0] * ia, o[dt][1] * ia);
        g_aoh[(mA + 8) * 512 + ci] = packh(o[dt][2] * ib, o[dt][3] * ib);
    }
}

// ---------------------------------------------------------------------------
extern "C" void kernel_launch(void* const* d_in, const int* in_sizes, int n_in,
                              void* d_out, int out_size)
{
    const float* x      = (const float*)d_in[0];
    const float* w_qkv  = (const float*)d_in[1];
    const float* w_proj = (const float*)d_in[2];
    const float* b_proj = (const float*)d_in[3];
    float* out = (float*)d_out;

    void *pxh, *pwqh, *pwph, *pqh, *paoh;
    cudaGetSymbolAddress(&pxh, g_xh);
    cudaGetSymbolAddress(&pwqh, g_wqh);
    cudaGetSymbolAddress(&pwph, g_wph);
    cudaGetSymbolAddress(&pqh, g_qkvh);
    cudaGetSymbolAddress(&paoh, g_aoh);

    cudaFuncSetAttribute((const void*)mm1<0>, cudaFuncAttributeMaxDynamicSharedMemorySize, 98304);
    cudaFuncSetAttribute((const void*)mm1<1>, cudaFuncAttributeMaxDynamicSharedMemorySize, 98304);
    cudaFuncSetAttribute(flash1, cudaFuncAttributeMaxDynamicSharedMemorySize, 81920);

    // 1) Round everything to fp16 1-digit (single launch)
    round_all<<<8192, 256>>>(x, w_qkv, w_proj,
                             (uint32_t*)pxh, (uint32_t*)pwqh, (uint32_t*)pwph);

    // 2) QKV projection -> fp16 Q/K/V (Q scaled by 0.125*log2e)
    mm1<0><<<dim3(24, 32), 256, 98304>>>(
        (uint32_t*)pxh, (uint32_t*)pwqh, nullptr, nullptr,
        (uint32_t*)pqh, 3072, 1024);

    // 3) Attention (base-2 softmax) -> fp16 AO
    flash1<<<dim3(8, 32), 512, 81920>>>();

    // 4) Output projection + bias
    mm1<1><<<dim3(8, 32), 256, 98304>>>(
        (uint32_t*)paoh, (uint32_t*)pwph, b_proj, out,
        nullptr, 1024, 1024);
}

// round 16
// speedup vs baseline: 2.8498x; 1.0684x over previous
#include <cuda_runtime.h>
#include <cuda_fp16.h>
#include <cstdint>

#define DIM    1024
#define NHEADS 16
#define HDIM   64
#define BATCH  2
#define SEQ    2048
#define MROWS  4096

// ---------------------------------------------------------------------------
// Global scratch (static; no runtime allocation). Everything fp16 1-digit.
// QKV: [s(3)][bh(32)][seq(2048)][32 u32], Q pre-scaled by 0.125*log2(e).
// ---------------------------------------------------------------------------
__device__ __align__(128) uint32_t g_xh [MROWS * 512];
__device__ __align__(128) uint32_t g_wqh[3072 * 512];
__device__ __align__(128) uint32_t g_wph[1024 * 512];
__device__ __align__(128) uint32_t g_aoh[MROWS * 512];
__device__ __align__(128) uint32_t g_qkvh[3u * 2097152];

// ---------------------------------------------------------------------------
// Helpers
// ---------------------------------------------------------------------------
__device__ __forceinline__ uint32_t smem_u32(const void* p) {
    uint32_t a;
    asm("{ .reg .u64 t; cvta.to.shared.u64 t, %1; cvt.u32.u64 %0, t; }" : "=r"(a) : "l"(p));
    return a;
}
__device__ __forceinline__ void ldsm4(uint32_t r[4], uint32_t addr) {
    asm volatile("ldmatrix.sync.aligned.m8n8.x4.shared.b16 {%0,%1,%2,%3}, [%4];"
                 : "=r"(r[0]), "=r"(r[1]), "=r"(r[2]), "=r"(r[3]) : "r"(addr));
}
__device__ __forceinline__ void ldsm4t(uint32_t r[4], uint32_t addr) {
    asm volatile("ldmatrix.sync.aligned.m8n8.x4.trans.shared.b16 {%0,%1,%2,%3}, [%4];"
                 : "=r"(r[0]), "=r"(r[1]), "=r"(r[2]), "=r"(r[3]) : "r"(addr));
}
__device__ __forceinline__ void mma_h(float c[4], const uint32_t a[4], const uint32_t b[2]) {
    asm volatile(
        "mma.sync.aligned.m16n8k16.row.col.f32.f16.f16.f32 "
        "{%0,%1,%2,%3}, {%4,%5,%6,%7}, {%8,%9}, {%0,%1,%2,%3};"
        : "+f"(c[0]), "+f"(c[1]), "+f"(c[2]), "+f"(c[3])
        : "r"(a[0]), "r"(a[1]), "r"(a[2]), "r"(a[3]), "r"(b[0]), "r"(b[1]));
}
__device__ __forceinline__ uint32_t packh(float x, float y) {
    __half hx = __float2half_rn(x), hy = __float2half_rn(y);
    return (uint32_t)__half_as_ushort(hx) | ((uint32_t)__half_as_ushort(hy) << 16);
}
__device__ __forceinline__ float ex2f(float x) {
    float r;
    asm("ex2.approx.ftz.f32 %0, %1;" : "=f"(r) : "f"(x));
    return r;
}
__device__ __forceinline__ void cpa16(uint32_t dst, const void* src) {
    asm volatile("cp.async.cg.shared.global [%0], [%1], 16;" :: "r"(dst), "l"(src));
}
#define CP_COMMIT() asm volatile("cp.async.commit_group;" ::: "memory")
#define CP_WAIT(n)  asm volatile("cp.async.wait_group %0;" :: "n"(n) : "memory")

// ---------------------------------------------------------------------------
// round_all: fp32 -> fp16 1-digit for all three inputs in ONE launch.
// Blocks [0,4096): x; [4096,7168): w_qkv; [7168,8192): w_proj.
// ---------------------------------------------------------------------------
__global__ __launch_bounds__(256)
void round_all(const float* __restrict__ x, const float* __restrict__ wq,
               const float* __restrict__ wp,
               uint32_t* __restrict__ xh, uint32_t* __restrict__ wqh,
               uint32_t* __restrict__ wph)
{
    int blk = blockIdx.x;
    const float* in;
    uint32_t* outp;
    int gbase;
    if (blk < 4096)      { in = x;  outp = xh;  gbase = blk; }
    else if (blk < 7168) { in = wq; outp = wqh; gbase = blk - 4096; }
    else                 { in = wp; outp = wph; gbase = blk - 7168; }
    int g = gbase * 256 + threadIdx.x;
    float4 v = ((const float4*)in)[g];
    ((uint2*)outp)[g] = make_uint2(packh(v.x, v.y), packh(v.z, v.w));
}

// ---------------------------------------------------------------------------
// GEMM: C[M,N] = A[M,K] @ B[N,K]^T, fp16 1-digit, 1 MMA/tile.
// Block 128x128, 256 thr (8 warps, 64x32 warp tile), BK=64, 3-stage cp.async,
// 2 CTAs/SM. smem/stage 32KB: A +0 (16KB), B +16384.
// EPI 0: scatter fp16 QKV (Q scaled 0.125*log2e). EPI 1: fp32 + bias.
// ---------------------------------------------------------------------------
template <int EPI>
__global__ __launch_bounds__(256, 2)
void mm1(const uint32_t* __restrict__ Ah, const uint32_t* __restrict__ Bh,
         const float* __restrict__ bias, float* __restrict__ Cout,
         uint32_t* __restrict__ qh, int N, int K)
{
    extern __shared__ __align__(128) uint32_t sm[];
    const int tid = threadIdx.x, lane = tid & 31, wid = tid >> 5;
    const int m0 = blockIdx.y * 128, n0 = blockIdx.x * 128;
    const int wm = (wid & 1) * 64, wn = (wid >> 1) * 32;
    const uint32_t base = smem_u32(sm);
    const int T  = K >> 6;   // k64 steps
    const int KC = K >> 3;   // 16B chunks per row

    const int arow = lane & 15, aco = lane >> 4;
    const int brow = (lane & 7) | ((lane & 16) >> 1), bco = (lane & 8) >> 3;

    auto issue = [&](int t) {
        int st  = t % 3;
        int kc0 = t << 3;
        #pragma unroll
        for (int it = 0; it < 8; it++) {
            int idx = tid + it * 256;              // 0..2047: A then B
            int blk = idx >> 10;
            int row = (idx >> 3) & 127;
            int ch  = idx & 7;
            const uint32_t* sp = blk ? Bh : Ah;
            int grow = (blk ? n0 : m0) + row;
            const void* src = sp + ((size_t)grow * KC + kc0 + ch) * 4;
            uint32_t dst = base + st * 32768 + blk * 16384
                         + row * 128 + ((ch ^ (row & 7)) * 16);
            cpa16(dst, src);
        }
    };

    float acc[4][4][4] = {};

    issue(0); CP_COMMIT();
    issue(1); CP_COMMIT();

    for (int t = 0; t < T; t++) {
        if (t + 2 < T) { issue(t + 2); CP_COMMIT(); CP_WAIT(2); }
        else           { CP_WAIT(0); }
        __syncthreads();

        const uint32_t sOff = base + (t % 3) * 32768;
        #pragma unroll
        for (int kk = 0; kk < 4; kk++) {
            uint32_t aH[4][4], bH[2][4];
            #pragma unroll
            for (int mt = 0; mt < 4; mt++) {
                int r = wm + mt * 16 + arow;
                int c = (kk * 2 + aco) ^ (r & 7);
                ldsm4(aH[mt], sOff + r * 128 + c * 16);
            }
            #pragma unroll
            for (int g = 0; g < 2; g++) {
                int r = wn + g * 16 + brow;
                int c = (kk * 2 + bco) ^ (r & 7);
                ldsm4(bH[g], sOff + 16384 + r * 128 + c * 16);
            }
            #pragma unroll
            for (int mt = 0; mt < 4; mt++)
                #pragma unroll
                for (int nt = 0; nt < 4; nt++)
                    mma_h(acc[mt][nt], aH[mt], &bH[nt >> 1][(nt & 1) * 2]);
        }
        __syncthreads();
    }

    const int r = lane >> 2, j = (lane & 3) * 2;
    if (EPI == 0) {
        const int sidx = n0 >> 10;
        // Q pre-scale folds 1/sqrt(64) and log2(e) for base-2 softmax
        const float qs = (sidx == 0) ? 0.125f * 1.44269504f : 1.0f;
        uint32_t* H = qh + (size_t)sidx * 2097152;
        #pragma unroll
        for (int mt = 0; mt < 4; mt++) {
            int mA = m0 + wm + mt * 16 + r;
            int b  = mA >> 11, q = mA & 2047;
            #pragma unroll
            for (int nt = 0; nt < 4; nt++) {
                int n = n0 + wn + nt * 8 + j;
                int rin = n & 1023, h = rin >> 6, d = rin & 63;
                size_t o1 = (((size_t)(b * 16 + h)) * 2048 + q) * 32 + (d >> 1);
                H[o1]          = packh(acc[mt][nt][0] * qs, acc[mt][nt][1] * qs);
                H[o1 + 8 * 32] = packh(acc[mt][nt][2] * qs, acc[mt][nt][3] * qs);
            }
        }
    } else {
        #pragma unroll
        for (int mt = 0; mt < 4; mt++) {
            int mA = m0 + wm + mt * 16 + r;
            #pragma unroll
            for (int nt = 0; nt < 4; nt++) {
                int c = n0 + wn + nt * 8 + j;
                float b0 = bias[c], b1 = bias[c + 1];
                *(float2*)(Cout + (size_t)mA * N + c) =
                    make_float2(acc[mt][nt][0] + b0, acc[mt][nt][1] + b1);
                *(float2*)(Cout + (size_t)(mA + 8) * N + c) =
                    make_float2(acc[mt][nt][2] + b0, acc[mt][nt][3] + b1);
            }
        }
    }
}

// ---------------------------------------------------------------------------
// Flash attention, plain fp16 HMMA, base-2 online softmax (ex2.approx).
// Block = 128 queries of one (b,h), 256 thr / 8 warps (warp owns 16 rows),
// 2 CTAs/SM (phase overlap: one CTA's MMA burst covers the other's softmax).
// smem: Q 0 (16KB); KV stage s at 16384+s*16384: K +0 (8KB), V +8192.
// Total 64KB. 3-stage ring, 1 sync/iter. Epilogue writes fp16 1-digit AO.
// ---------------------------------------------------------------------------
__global__ __launch_bounds__(256, 2)
void flash1()
{
    extern __shared__ __align__(128) uint32_t sm[];
    const int tid = threadIdx.x, lane = tid & 31, w = tid >> 5;
    const int bh = blockIdx.y, b = bh >> 4, h = bh & 15;
    const int q0 = blockIdx.x * 128;
    const uint32_t base = smem_u32(sm);

    const int arow = lane & 15, aco = lane >> 4;
    const int brow = (lane & 7) | ((lane & 16) >> 1), bco = (lane & 8) >> 3;

    // Q preload: 1024 16B-chunks (128 rows x 8)
    #pragma unroll
    for (int it = 0; it < 4; it++) {
        int idx = tid + it * 256;
        int row = (idx >> 3) & 127, ch = idx & 7;
        const void* src = g_qkvh + ((size_t)bh * 2048 + q0 + row) * 32 + ch * 4;
        uint32_t dst = base + row * 128 + ((ch ^ (row & 7)) * 16);
        cpa16(dst, src);
    }
    CP_COMMIT();

    // KV stage: K (8KB) + V (8KB) = 1024 chunks
    auto issueKV = [&](int t) {
        int st = t % 3, s0 = t * 64;
        #pragma unroll
        for (int it = 0; it < 4; it++) {
            int idx = tid + it * 256;              // 0..1023
            int part = idx >> 9;                   // 0=K, 1=V
            int row = (idx >> 3) & 63, ch = idx & 7;
            const void* src = g_qkvh + (size_t)(1 + part) * 2097152
                            + ((size_t)bh * 2048 + s0 + row) * 32 + ch * 4;
            uint32_t dst = base + 16384 + st * 16384 + part * 8192
                         + row * 128 + ((ch ^ (row & 7)) * 16);
            cpa16(dst, src);
        }
    };

    issueKV(0); CP_COMMIT();

    float m_a = -1e30f, m_b = -1e30f, l_a = 0.f, l_b = 0.f;
    float o[8][4] = {};

    const int NT = SEQ / 64;   // 32
    for (int t = 0; t < NT; t++) {
        if (t + 1 < NT) { issueKV(t + 1); CP_COMMIT(); CP_WAIT(1); }
        else            { CP_WAIT(0); }
        __syncthreads();

        const uint32_t kBase = base + 16384 + (t % 3) * 16384;
        const uint32_t vBase = kBase + 8192;

        // S = Q K^T (log2 domain), 1 MMA/tile
        float s[8][4] = {};
        #pragma unroll
        for (int kk = 0; kk < 4; kk++) {
            uint32_t aH[4];
            {
                int r = w * 16 + arow;
                int c = (kk * 2 + aco) ^ (r & 7);
                ldsm4(aH, base + r * 128 + c * 16);
            }
            #pragma unroll
            for (int g = 0; g < 4; g++) {
                int rb = g * 16 + brow;
                int cb = (kk * 2 + bco) ^ (rb & 7);
                uint32_t bK[4];
                ldsm4(bK, kBase + rb * 128 + cb * 16);
                mma_h(s[2 * g],     aH, &bK[0]);
                mma_h(s[2 * g + 1], aH, &bK[2]);
            }
        }

        // Online softmax, base 2 (rows lane>>2 and +8; 4-lane group reduce)
        float mxa = -1e30f, mxb = -1e30f;
        #pragma unroll
        for (int nt = 0; nt < 8; nt++) {
            mxa = fmaxf(mxa, fmaxf(s[nt][0], s[nt][1]));
            mxb = fmaxf(mxb, fmaxf(s[nt][2], s[nt][3]));
        }
        mxa = fmaxf(mxa, __shfl_xor_sync(0xffffffffu, mxa, 1));
        mxa = fmaxf(mxa, __shfl_xor_sync(0xffffffffu, mxa, 2));
        mxb = fmaxf(mxb, __shfl_xor_sync(0xffffffffu, mxb, 1));
        mxb = fmaxf(mxb, __shfl_xor_sync(0xffffffffu, mxb, 2));
        float mna = fmaxf(m_a, mxa), mnb = fmaxf(m_b, mxb);
        float alA = ex2f(m_a - mna), alB = ex2f(m_b - mnb);
        m_a = mna; m_b = mnb;
        float suma = 0.f, sumb = 0.f;
        #pragma unroll
        for (int nt = 0; nt < 8; nt++) {
            s[nt][0] = ex2f(s[nt][0] - mna); suma += s[nt][0];
            s[nt][1] = ex2f(s[nt][1] - mna); suma += s[nt][1];
            s[nt][2] = ex2f(s[nt][2] - mnb); sumb += s[nt][2];
            s[nt][3] = ex2f(s[nt][3] - mnb); sumb += s[nt][3];
        }
        suma += __shfl_xor_sync(0xffffffffu, suma, 1);
        suma += __shfl_xor_sync(0xffffffffu, suma, 2);
        sumb += __shfl_xor_sync(0xffffffffu, sumb, 1);
        sumb += __shfl_xor_sync(0xffffffffu, sumb, 2);
        l_a = l_a * alA + suma;
        l_b = l_b * alB + sumb;
        #pragma unroll
        for (int dt = 0; dt < 8; dt++) {
            o[dt][0] *= alA; o[dt][1] *= alA;
            o[dt][2] *= alB; o[dt][3] *= alB;
        }

        // O += P V  (both fp16 1-digit; 1 MMA/tile)
        #pragma unroll
        for (int kc = 0; kc < 4; kc++) {
            uint32_t pH[4];
            pH[0] = packh(s[2 * kc][0],     s[2 * kc][1]);
            pH[1] = packh(s[2 * kc][2],     s[2 * kc][3]);
            pH[2] = packh(s[2 * kc + 1][0], s[2 * kc + 1][1]);
            pH[3] = packh(s[2 * kc + 1][2], s[2 * kc + 1][3]);
            int rv = kc * 16 + arow;
            #pragma unroll
            for (int g = 0; g < 4; g++) {
                int cv = (g * 2 + aco) ^ (rv & 7);
                uint32_t vf[4];
                ldsm4t(vf, vBase + rv * 128 + cv * 16);
                mma_h(o[2 * g],     pH, &vf[0]);
                mma_h(o[2 * g + 1], pH, &vf[2]);
            }
        }
        // NOTE: no bottom barrier — 3-stage KV ring makes it safe.
    }

    // Epilogue: normalize, pack fp16 1-digit to g_aoh [m][512]
    float ia = 1.f / l_a, ib = 1.f / l_b;
    size_t mA = (size_t)b * SEQ + q0 + w * 16 + (lane >> 2);
    #pragma unroll
    for (int dt = 0; dt < 8; dt++) {
        int c  = dt * 8 + (lane & 3) * 2;
        int ci = h * 32 + (c >> 1);
        g_aoh[mA * 512 + ci]       = packh(o[dt][0] * ia, o[dt][1] * ia);
        g_aoh[(mA + 8) * 512 + ci] = packh(o[dt][2] * ib, o[dt][3] * ib);
    }
}

// ---------------------------------------------------------------------------
extern "C" void kernel_launch(void* const* d_in, const int* in_sizes, int n_in,
                              void* d_out, int out_size)
{
    const float* x      = (const float*)d_in[0];
    const float* w_qkv  = (const float*)d_in[1];
    const float* w_proj = (const float*)d_in[2];
    const float* b_proj = (const float*)d_in[3];
    float* out = (float*)d_out;

    void *pxh, *pwqh, *pwph, *pqh, *paoh;
    cudaGetSymbolAddress(&pxh, g_xh);
    cudaGetSymbolAddress(&pwqh, g_wqh);
    cudaGetSymbolAddress(&pwph, g_wph);
    cudaGetSymbolAddress(&pqh, g_qkvh);
    cudaGetSymbolAddress(&paoh, g_aoh);

    cudaFuncSetAttribute((const void*)mm1<0>, cudaFuncAttributeMaxDynamicSharedMemorySize, 98304);
    cudaFuncSetAttribute((const void*)mm1<1>, cudaFuncAttributeMaxDynamicSharedMemorySize, 98304);
    cudaFuncSetAttribute(flash1, cudaFuncAttributeMaxDynamicSharedMemorySize, 65536);

    // 1) Round everything to fp16 1-digit (single launch)
    round_all<<<8192, 256>>>(x, w_qkv, w_proj,
                             (uint32_t*)pxh, (uint32_t*)pwqh, (uint32_t*)pwph);

    // 2) QKV projection -> fp16 Q/K/V (Q scaled by 0.125*log2e)
    mm1<0><<<dim3(24, 32), 256, 98304>>>(
        (uint32_t*)pxh, (uint32_t*)pwqh, nullptr, nullptr,
        (uint32_t*)pqh, 3072, 1024);

    // 3) Attention (base-2 softmax, 2 CTAs/SM) -> fp16 AO
    flash1<<<dim3(16, 32), 256, 65536>>>();

    // 4) Output projection + bias
    mm1<1><<<dim3(8, 32), 256, 98304>>>(
        (uint32_t*)paoh, (uint32_t*)pwph, b_proj, out,
        nullptr, 1024, 1024);
}